// round 1
// baseline (speedup 1.0000x reference)
#include <cuda_runtime.h>
#include <cstdint>

// Problem constants
#define B_ 4
#define S_ 2048
#define D_ 1024

// Scratch (device globals: allocation-free per harness rules)
__device__ float g_WQ[B_ * S_ * D_];        // 32 MB
__device__ float g_WKV[B_ * S_ * D_];       // 32 MB
__device__ float g_scores[(size_t)B_ * S_ * S_]; // 64 MB (scores, then attn in-place)

// ---------------------------------------------------------------------------
// TF32 helpers
// ---------------------------------------------------------------------------
__device__ __forceinline__ uint32_t f2tf32(float x) {
    uint32_t r;
    asm("cvt.rna.tf32.f32 %0, %1;" : "=r"(r) : "f"(x));
    return r;
}

__device__ __forceinline__ void mma_tf32(float* c, const uint32_t* a, const uint32_t* b) {
    asm volatile(
        "mma.sync.aligned.m16n8k8.row.col.f32.tf32.tf32.f32 "
        "{%0,%1,%2,%3}, {%4,%5,%6,%7}, {%8,%9}, {%0,%1,%2,%3};"
        : "+f"(c[0]), "+f"(c[1]), "+f"(c[2]), "+f"(c[3])
        : "r"(a[0]), "r"(a[1]), "r"(a[2]), "r"(a[3]),
          "r"(b[0]), "r"(b[1]));
}

// ---------------------------------------------------------------------------
// Generic TF32 GEMM: C = scale * A[M,K] @ B   (B is [K,N] or, if TRANS_B, [N,K])
// Block tile 128x128, BK=32, 256 threads (8 warps as 2x4, warp tile 64x32).
// CAUSAL: skip output tiles strictly above the diagonal (scores GEMM).
// LIMITK: truncate K loop at (bm+1)*128 (out GEMM; attn is causally zero beyond).
// ---------------------------------------------------------------------------
#define BM 128
#define BN 128
#define BK 32
#define SKP (BK + 4)   // pad 4 -> conflict-free fragment LDS

template <bool TRANS_B, bool CAUSAL, bool LIMITK>
__global__ void __launch_bounds__(256)
gemm_tf32(const float* __restrict__ A, const float* __restrict__ Bm,
          float* __restrict__ C,
          int K, int lda, int ldb, int ldc, float scale,
          size_t aBatch, size_t bBatch, size_t cBatch)
{
    const int bm = blockIdx.y;
    const int bn = blockIdx.x;
    if (CAUSAL && bn > bm) return;   // all threads exit before any barrier

    const float* Ab = A + aBatch * blockIdx.z;
    const float* Bb = Bm + bBatch * blockIdx.z;
    float*       Cb = C + cBatch * blockIdx.z;

    const int kEnd = LIMITK ? min(K, (bm + 1) * BM) : K;

    __shared__ __align__(16) uint32_t sA[BM][SKP];
    __shared__ __align__(16) uint32_t sB[BN][SKP];

    const int warp = threadIdx.x >> 5;
    const int lane = threadIdx.x & 31;
    const int wm = (warp >> 2) * 64;   // warp row base within block tile
    const int wn = (warp & 3) * 32;    // warp col base
    const int g  = lane >> 2;          // groupID (0..7)
    const int tq = lane & 3;           // thread-in-group (0..3)

    float acc[4][4][4] = {};

    for (int k0 = 0; k0 < kEnd; k0 += BK) {
        // ---- load A tile [BM x BK] (row-major, k contiguous) ----
        {
            const int r = threadIdx.x >> 3;          // 0..31
            const int c = (threadIdx.x & 7) * 4;     // 0..28
            #pragma unroll
            for (int i = 0; i < 4; i++) {
                const int row = r + i * 32;
                const float4 v = *reinterpret_cast<const float4*>(
                    &Ab[(size_t)(bm * BM + row) * lda + k0 + c]);
                uint4 u;
                u.x = f2tf32(v.x); u.y = f2tf32(v.y);
                u.z = f2tf32(v.z); u.w = f2tf32(v.w);
                *reinterpret_cast<uint4*>(&sA[row][c]) = u;
            }
        }
        // ---- load B tile into sB[n][k] ----
        if (TRANS_B) {
            // B is [N,K] row-major: same pattern as A
            const int r = threadIdx.x >> 3;
            const int c = (threadIdx.x & 7) * 4;
            #pragma unroll
            for (int i = 0; i < 4; i++) {
                const int row = r + i * 32;
                const float4 v = *reinterpret_cast<const float4*>(
                    &Bb[(size_t)(bn * BN + row) * ldb + k0 + c]);
                uint4 u;
                u.x = f2tf32(v.x); u.y = f2tf32(v.y);
                u.z = f2tf32(v.z); u.w = f2tf32(v.w);
                *reinterpret_cast<uint4*>(&sB[row][c]) = u;
            }
        } else {
            // B is [K,N] row-major: coalesced float4 along n, transpose into smem
            const int kr = threadIdx.x >> 5;         // 0..7
            const int nc = (threadIdx.x & 31) * 4;   // 0..124
            #pragma unroll
            for (int i = 0; i < 4; i++) {
                const int kk = kr + i * 8;
                const float4 v = *reinterpret_cast<const float4*>(
                    &Bb[(size_t)(k0 + kk) * ldb + bn * BN + nc]);
                sB[nc + 0][kk] = f2tf32(v.x);
                sB[nc + 1][kk] = f2tf32(v.y);
                sB[nc + 2][kk] = f2tf32(v.z);
                sB[nc + 3][kk] = f2tf32(v.w);
            }
        }
        __syncthreads();

        #pragma unroll
        for (int ks = 0; ks < BK; ks += 8) {
            uint32_t af[4][4];
            #pragma unroll
            for (int mi = 0; mi < 4; mi++) {
                const int row = wm + mi * 16;
                af[mi][0] = sA[row + g    ][ks + tq    ];
                af[mi][1] = sA[row + g + 8][ks + tq    ];
                af[mi][2] = sA[row + g    ][ks + tq + 4];
                af[mi][3] = sA[row + g + 8][ks + tq + 4];
            }
            uint32_t bf[4][2];
            #pragma unroll
            for (int ni = 0; ni < 4; ni++) {
                const int col = wn + ni * 8;
                bf[ni][0] = sB[col + g][ks + tq    ];
                bf[ni][1] = sB[col + g][ks + tq + 4];
            }
            #pragma unroll
            for (int mi = 0; mi < 4; mi++)
                #pragma unroll
                for (int ni = 0; ni < 4; ni++)
                    mma_tf32(acc[mi][ni], af[mi], bf[ni]);
        }
        __syncthreads();
    }

    // ---- epilogue ----
    #pragma unroll
    for (int mi = 0; mi < 4; mi++) {
        #pragma unroll
        for (int ni = 0; ni < 4; ni++) {
            const int row0 = bm * BM + wm + mi * 16 + g;
            const int col  = bn * BN + wn + ni * 8 + tq * 2;
            float2 v0 = make_float2(acc[mi][ni][0] * scale, acc[mi][ni][1] * scale);
            float2 v1 = make_float2(acc[mi][ni][2] * scale, acc[mi][ni][3] * scale);
            *reinterpret_cast<float2*>(&Cb[(size_t)row0 * ldc + col])       = v0;
            *reinterpret_cast<float2*>(&Cb[(size_t)(row0 + 8) * ldc + col]) = v1;
        }
    }
}

// ---------------------------------------------------------------------------
// Causal row softmax (in place). Row q of batch b: valid keys are [0, q].
// Writes zeros for j in (q, diag-tile end) so the out-GEMM's truncated K-loop
// reads exact zeros on the masked part of the diagonal tile.
// ---------------------------------------------------------------------------
__global__ void __launch_bounds__(256) softmax_causal(float* __restrict__ scores)
{
    __shared__ float red[8];
    __shared__ float bcast;

    const int q = blockIdx.x;
    float* row = scores + ((size_t)blockIdx.y * S_ + q) * S_;
    const int len = q + 1;
    const int tid = threadIdx.x;

    // max
    float m = -3.4e38f;
    for (int i = tid; i < len; i += 256) m = fmaxf(m, row[i]);
    #pragma unroll
    for (int o = 16; o; o >>= 1) m = fmaxf(m, __shfl_xor_sync(0xffffffffu, m, o));
    if ((tid & 31) == 0) red[tid >> 5] = m;
    __syncthreads();
    if (tid == 0) {
        float v = red[0];
        #pragma unroll
        for (int i = 1; i < 8; i++) v = fmaxf(v, red[i]);
        bcast = v;
    }
    __syncthreads();
    m = bcast;

    // sum of exp
    float sum = 0.f;
    for (int i = tid; i < len; i += 256) sum += __expf(row[i] - m);
    #pragma unroll
    for (int o = 16; o; o >>= 1) sum += __shfl_xor_sync(0xffffffffu, sum, o);
    __syncthreads();
    if ((tid & 31) == 0) red[tid >> 5] = sum;
    __syncthreads();
    if (tid == 0) {
        float v = 0.f;
        #pragma unroll
        for (int i = 0; i < 8; i++) v += red[i];
        bcast = 1.f / v;
    }
    __syncthreads();
    const float inv = bcast;

    const int tileEnd = ((q >> 7) + 1) << 7;   // end of the diagonal 128-tile
    for (int i = tid; i < tileEnd; i += 256)
        row[i] = (i < len) ? __expf(row[i] - m) * inv : 0.f;
}

// ---------------------------------------------------------------------------
// Launch
// ---------------------------------------------------------------------------
extern "C" void kernel_launch(void* const* d_in, const int* in_sizes, int n_in,
                              void* d_out, int out_size)
{
    (void)in_sizes; (void)n_in; (void)out_size;
    const float* q  = (const float*)d_in[0];
    const float* Wq = (const float*)d_in[1];
    // d_in[2] = Wk (unused by reference), d_in[4] = mask (causal, handled analytically)
    const float* Wv = (const float*)d_in[3];
    float* out = (float*)d_out;

    float *pWQ, *pWKV, *pS;
    cudaGetSymbolAddress((void**)&pWQ,  g_WQ);
    cudaGetSymbolAddress((void**)&pWKV, g_WKV);
    cudaGetSymbolAddress((void**)&pS,   g_scores);

    const dim3 blk(256);

    // 1) Projections: WQ = q@Wq, WKV = q@Wv   ([8192,1024] @ [1024,1024])
    {
        const dim3 grid(D_ / BN, (B_ * S_) / BM, 1);
        gemm_tf32<false, false, false><<<grid, blk>>>(
            q, Wq, pWQ, D_, D_, D_, D_, 1.0f, 0, 0, 0);
        gemm_tf32<false, false, false><<<grid, blk>>>(
            q, Wv, pWKV, D_, D_, D_, D_, 1.0f, 0, 0, 0);
    }

    // 2) Scores = WQ @ WKV^T / sqrt(D), lower-triangle tiles only
    {
        const dim3 grid(S_ / BN, S_ / BM, B_);
        gemm_tf32<true, true, false><<<grid, blk>>>(
            pWQ, pWKV, pS, D_, D_, D_, S_, 1.0f / 32.0f,
            (size_t)S_ * D_, (size_t)S_ * D_, (size_t)S_ * S_);
    }

    // 3) Causal softmax in place
    {
        const dim3 grid(S_, B_);
        softmax_causal<<<grid, blk>>>(pS);
    }

    // 4) out = attn @ WKV, K-loop truncated causally per query tile
    {
        const dim3 grid(D_ / BN, S_ / BM, B_);
        gemm_tf32<false, false, true><<<grid, blk>>>(
            pS, pWKV, out, S_, S_, D_, D_, 1.0f,
            (size_t)S_ * S_, (size_t)S_ * D_, (size_t)S_ * D_);
    }
}

// round 3
// speedup vs baseline: 1.7333x; 1.7333x over previous
#include <cuda_runtime.h>
#include <cstdint>

// Problem constants
#define B_ 4
#define S_ 2048
#define D_ 1024

// Scratch (device globals: allocation-free per harness rules)
__device__ float g_q32[B_ * S_ * D_];            // 32 MB  q rounded to tf32
__device__ float g_WqT[D_ * D_];                 // 4 MB   Wq^T rounded
__device__ float g_WvT[D_ * D_];                 // 4 MB   Wv^T rounded
__device__ float g_WQ [B_ * S_ * D_];            // 32 MB  (rounded at epilogue)
__device__ float g_WKV[B_ * S_ * D_];            // 32 MB  (rounded at epilogue)
__device__ float g_WKVt[B_ * S_ * D_];           // 32 MB  WKV^T per batch
__device__ float g_scores[(size_t)B_ * S_ * S_]; // 64 MB  scores -> attn in place

// ---------------------------------------------------------------------------
// Helpers
// ---------------------------------------------------------------------------
__device__ __forceinline__ float rtf(float x) {  // round fp32 -> tf32-valued fp32
    uint32_t u;
    asm("cvt.rna.tf32.f32 %0, %1;" : "=r"(u) : "f"(x));
    return __uint_as_float(u);
}

__device__ __forceinline__ uint32_t smem_u32(const void* p) {
    uint32_t a;
    asm("{ .reg .u64 t; cvta.to.shared.u64 t, %1; cvt.u32.u64 %0, t; }" : "=r"(a) : "l"(p));
    return a;
}

__device__ __forceinline__ void mma_tf32(float* c, const uint32_t* a, const uint32_t* b) {
    asm volatile(
        "mma.sync.aligned.m16n8k8.row.col.f32.tf32.tf32.f32 "
        "{%0,%1,%2,%3}, {%4,%5,%6,%7}, {%8,%9}, {%0,%1,%2,%3};"
        : "+f"(c[0]), "+f"(c[1]), "+f"(c[2]), "+f"(c[3])
        : "r"(a[0]), "r"(a[1]), "r"(a[2]), "r"(a[3]),
          "r"(b[0]), "r"(b[1]));
}

#define CP_ASYNC16(dst_u32, src_ptr) \
    asm volatile("cp.async.cg.shared.global [%0], [%1], 16;" \
        :: "r"(dst_u32), "l"(src_ptr) : "memory")
#define CP_COMMIT() asm volatile("cp.async.commit_group;" ::: "memory")
#define CP_WAIT1()  asm volatile("cp.async.wait_group 1;"  ::: "memory")

// ---------------------------------------------------------------------------
// Pipelined TF32 GEMM: C = scale * A[M,K] @ B^T, B given as [N,K] (k-contig).
// All inputs already tf32-rounded. CTA tile 128x128, KC=32, 3-stage cp.async.
// CAUSAL: skip tiles above diagonal.  LIMITK: truncate K at (bm+1)*128.
// ROUND_OUT: round epilogue output to tf32 values (for operands of later GEMMs).
// ---------------------------------------------------------------------------
#define BM 128
#define BN 128
#define KC 32
#define SKP 36                       // floats per smem row (pad: bank = 4g+tq, distinct)
#define STAGE_B (128 * SKP * 4)      // 18432 B per tile stage
#define BOFF    (3 * STAGE_B)        // B stages after A stages
#define SMEM_TOTAL (6 * STAGE_B)     // 110592 B

template <bool CAUSAL, bool LIMITK, bool ROUND_OUT>
__global__ void __launch_bounds__(256, 2)
gemm_pipe(const float* __restrict__ A, const float* __restrict__ Bn,
          float* __restrict__ C,
          int K, int lda, int ldb, int ldc, float scale,
          size_t aBatch, size_t bBatch, size_t cBatch)
{
    const int bm = blockIdx.y;
    const int bn = blockIdx.x;
    if (CAUSAL && bn > bm) return;   // whole CTA exits before any barrier

    extern __shared__ __align__(128) char smem[];
    const uint32_t sbase = smem_u32(smem);

    const int tid  = threadIdx.x;
    const int warp = tid >> 5;
    const int lane = tid & 31;
    const int wm = (warp >> 2) * 64;    // warp row base in tile
    const int wn = (warp & 3) * 32;     // warp col base
    const int g  = lane >> 2;
    const int tq = lane & 3;

    const float* Ab = A + aBatch * blockIdx.z + (size_t)(bm * BM) * lda;
    const float* Bb = Bn + bBatch * blockIdx.z + (size_t)(bn * BN) * ldb;
    float*       Cb = C + cBatch * blockIdx.z;

    const int kEnd = LIMITK ? min(K, (bm + 1) * BM) : K;
    const int nc = kEnd / KC;

    // per-thread cp.async granule coords: 1024 granules per tile, 4 per thread
    const int gr = tid >> 3;         // row 0..31 (+ i*32)
    const int gc = (tid & 7) * 4;    // float col 0..28

    float acc[4][4][4] = {};

    // stage loader (A and B tiles, 16B granules)
    auto issue_stage = [&](int c) {
        if (c < nc) {
            const int s = c % 3;
            const int k0 = c * KC;
            const uint32_t da0 = sbase + s * STAGE_B;
            const uint32_t db0 = sbase + BOFF + s * STAGE_B;
            #pragma unroll
            for (int i = 0; i < 4; i++) {
                const int row = gr + i * 32;
                CP_ASYNC16(da0 + row * (SKP * 4) + gc * 4, Ab + (size_t)row * lda + k0 + gc);
                CP_ASYNC16(db0 + row * (SKP * 4) + gc * 4, Bb + (size_t)row * ldb + k0 + gc);
            }
        }
        CP_COMMIT();
    };

    issue_stage(0);
    issue_stage(1);

    for (int c = 0; c < nc; c++) {
        CP_WAIT1();          // stage c arrived
        __syncthreads();     // visible to all warps; prior stage's LDS complete
        issue_stage(c + 2);  // refill the slot computed two iterations ago

        const int s = c % 3;
        const uint32_t* cA = (const uint32_t*)(smem + s * STAGE_B);
        const uint32_t* cB = (const uint32_t*)(smem + BOFF + s * STAGE_B);

        #pragma unroll
        for (int ks = 0; ks < KC; ks += 8) {
            uint32_t af[4][4];
            #pragma unroll
            for (int mi = 0; mi < 4; mi++) {
                const int row = wm + mi * 16;
                af[mi][0] = cA[(row + g    ) * SKP + ks + tq    ];
                af[mi][1] = cA[(row + g + 8) * SKP + ks + tq    ];
                af[mi][2] = cA[(row + g    ) * SKP + ks + tq + 4];
                af[mi][3] = cA[(row + g + 8) * SKP + ks + tq + 4];
            }
            uint32_t bf[4][2];
            #pragma unroll
            for (int ni = 0; ni < 4; ni++) {
                const int col = wn + ni * 8;
                bf[ni][0] = cB[(col + g) * SKP + ks + tq    ];
                bf[ni][1] = cB[(col + g) * SKP + ks + tq + 4];
            }
            #pragma unroll
            for (int mi = 0; mi < 4; mi++)
                #pragma unroll
                for (int ni = 0; ni < 4; ni++)
                    mma_tf32(acc[mi][ni], af[mi], bf[ni]);
        }
    }

    // ---- epilogue ----
    #pragma unroll
    for (int mi = 0; mi < 4; mi++) {
        #pragma unroll
        for (int ni = 0; ni < 4; ni++) {
            const int row0 = bm * BM + wm + mi * 16 + g;
            const int col  = bn * BN + wn + ni * 8 + tq * 2;
            float v0 = acc[mi][ni][0] * scale, v1 = acc[mi][ni][1] * scale;
            float v2 = acc[mi][ni][2] * scale, v3 = acc[mi][ni][3] * scale;
            if (ROUND_OUT) { v0 = rtf(v0); v1 = rtf(v1); v2 = rtf(v2); v3 = rtf(v3); }
            *reinterpret_cast<float2*>(&Cb[(size_t)row0 * ldc + col])       = make_float2(v0, v1);
            *reinterpret_cast<float2*>(&Cb[(size_t)(row0 + 8) * ldc + col]) = make_float2(v2, v3);
        }
    }
}

// ---------------------------------------------------------------------------
// Prepass: round-copy (fp32 -> tf32-valued fp32), vectorized
// ---------------------------------------------------------------------------
__global__ void __launch_bounds__(256) round_copy(const float4* __restrict__ src,
                                                  float4* __restrict__ dst, int n4)
{
    const int i = blockIdx.x * 256 + threadIdx.x;
    if (i < n4) {
        float4 v = src[i];
        v.x = rtf(v.x); v.y = rtf(v.y); v.z = rtf(v.z); v.w = rtf(v.w);
        dst[i] = v;
    }
}

// ---------------------------------------------------------------------------
// Tiled transpose + round: src[R][C] -> dst[C][R], batched over z
// ---------------------------------------------------------------------------
__global__ void __launch_bounds__(256) transpose_round(const float* __restrict__ src,
                                                       float* __restrict__ dst,
                                                       int R, int C)
{
    __shared__ float t[32][33];
    const size_t bofs = (size_t)blockIdx.z * R * C;
    src += bofs; dst += bofs;

    int x = blockIdx.x * 32 + threadIdx.x;
    int y = blockIdx.y * 32 + threadIdx.y;
    #pragma unroll
    for (int j = 0; j < 32; j += 8)
        t[threadIdx.y + j][threadIdx.x] = rtf(src[(size_t)(y + j) * C + x]);
    __syncthreads();
    x = blockIdx.y * 32 + threadIdx.x;
    y = blockIdx.x * 32 + threadIdx.y;
    #pragma unroll
    for (int j = 0; j < 32; j += 8)
        dst[(size_t)(y + j) * R + x] = t[threadIdx.x][threadIdx.y + j];
}

// ---------------------------------------------------------------------------
// Causal row softmax (in place); writes tf32-rounded probabilities and zeros
// up to the end of the diagonal 128-tile.
// ---------------------------------------------------------------------------
__global__ void __launch_bounds__(256) softmax_causal(float* __restrict__ scores)
{
    __shared__ float red[8];
    __shared__ float bcast;

    const int q = blockIdx.x;
    float* row = scores + ((size_t)blockIdx.y * S_ + q) * S_;
    const int len = q + 1;
    const int tid = threadIdx.x;

    float m = -3.4e38f;
    for (int i = tid; i < len; i += 256) m = fmaxf(m, row[i]);
    #pragma unroll
    for (int o = 16; o; o >>= 1) m = fmaxf(m, __shfl_xor_sync(0xffffffffu, m, o));
    if ((tid & 31) == 0) red[tid >> 5] = m;
    __syncthreads();
    if (tid == 0) {
        float v = red[0];
        #pragma unroll
        for (int i = 1; i < 8; i++) v = fmaxf(v, red[i]);
        bcast = v;
    }
    __syncthreads();
    m = bcast;

    float sum = 0.f;
    for (int i = tid; i < len; i += 256) sum += __expf(row[i] - m);
    #pragma unroll
    for (int o = 16; o; o >>= 1) sum += __shfl_xor_sync(0xffffffffu, sum, o);
    __syncthreads();
    if ((tid & 31) == 0) red[tid >> 5] = sum;
    __syncthreads();
    if (tid == 0) {
        float v = 0.f;
        #pragma unroll
        for (int i = 0; i < 8; i++) v += red[i];
        bcast = 1.f / v;
    }
    __syncthreads();
    const float inv = bcast;

    const int tileEnd = ((q >> 7) + 1) << 7;
    for (int i = tid; i < tileEnd; i += 256)
        row[i] = (i < len) ? rtf(__expf(row[i] - m) * inv) : 0.f;
}

// ---------------------------------------------------------------------------
// Launch
// ---------------------------------------------------------------------------
extern "C" void kernel_launch(void* const* d_in, const int* in_sizes, int n_in,
                              void* d_out, int out_size)
{
    (void)in_sizes; (void)n_in; (void)out_size;
    const float* q  = (const float*)d_in[0];
    const float* Wq = (const float*)d_in[1];
    // d_in[2] = Wk (unused by reference), d_in[4] = mask (causal, analytic)
    const float* Wv = (const float*)d_in[3];
    float* out = (float*)d_out;

    float *pq, *pWqT, *pWvT, *pWQ, *pWKV, *pWKVt, *pS;
    cudaGetSymbolAddress((void**)&pq,    g_q32);
    cudaGetSymbolAddress((void**)&pWqT,  g_WqT);
    cudaGetSymbolAddress((void**)&pWvT,  g_WvT);
    cudaGetSymbolAddress((void**)&pWQ,   g_WQ);
    cudaGetSymbolAddress((void**)&pWKV,  g_WKV);
    cudaGetSymbolAddress((void**)&pWKVt, g_WKVt);
    cudaGetSymbolAddress((void**)&pS,    g_scores);

    cudaFuncSetAttribute(gemm_pipe<false, false, true>,
                         cudaFuncAttributeMaxDynamicSharedMemorySize, SMEM_TOTAL);
    cudaFuncSetAttribute(gemm_pipe<true, false, false>,
                         cudaFuncAttributeMaxDynamicSharedMemorySize, SMEM_TOTAL);
    cudaFuncSetAttribute(gemm_pipe<false, true, false>,
                         cudaFuncAttributeMaxDynamicSharedMemorySize, SMEM_TOTAL);

    const dim3 blk(256);

    // 0) Prepass: round q; transpose+round Wq, Wv
    round_copy<<<(B_ * S_ * D_ / 4 + 255) / 256, blk>>>(
        (const float4*)q, (float4*)pq, B_ * S_ * D_ / 4);
    {
        const dim3 tgrid(D_ / 32, D_ / 32, 1);
        const dim3 tblk(32, 8);
        transpose_round<<<tgrid, tblk>>>(Wq, pWqT, D_, D_);
        transpose_round<<<tgrid, tblk>>>(Wv, pWvT, D_, D_);
    }

    // 1) Projections: WQ = q@Wq, WKV = q@Wv (B as [N,K]); outputs tf32-rounded
    {
        const dim3 grid(D_ / BN, (B_ * S_) / BM, 1);
        gemm_pipe<false, false, true><<<grid, blk, SMEM_TOTAL>>>(
            pq, pWqT, pWQ, D_, D_, D_, D_, 1.0f, 0, 0, 0);
        gemm_pipe<false, false, true><<<grid, blk, SMEM_TOTAL>>>(
            pq, pWvT, pWKV, D_, D_, D_, D_, 1.0f, 0, 0, 0);
    }

    // 1b) Transpose WKV per batch: [S,D] -> [D,S] (already rounded)
    {
        const dim3 tgrid(D_ / 32, S_ / 32, B_);
        const dim3 tblk(32, 8);
        transpose_round<<<tgrid, tblk>>>(pWKV, pWKVt, S_, D_);
    }

    // 2) Scores = WQ @ WKV^T / 32  (WKV is naturally [N,K]); lower triangle only
    {
        const dim3 grid(S_ / BN, S_ / BM, B_);
        gemm_pipe<true, false, false><<<grid, blk, SMEM_TOTAL>>>(
            pWQ, pWKV, pS, D_, D_, D_, S_, 1.0f / 32.0f,
            (size_t)S_ * D_, (size_t)S_ * D_, (size_t)S_ * S_);
    }

    // 3) Causal softmax in place (rounds attn to tf32)
    {
        const dim3 grid(S_, B_);
        softmax_causal<<<grid, blk>>>(pS);
    }

    // 4) out = attn @ WKV  (B = WKV^T as [N=D, K=S]); K truncated causally
    {
        const dim3 grid(D_ / BN, S_ / BM, B_);
        gemm_pipe<false, true, false><<<grid, blk, SMEM_TOTAL>>>(
            pS, pWKVt, out, S_, S_, S_, D_, 1.0f,
            (size_t)S_ * S_, (size_t)S_ * D_, (size_t)S_ * D_);
    }
}

// round 4
// speedup vs baseline: 3.4750x; 2.0048x over previous
#include <cuda_runtime.h>
#include <cuda_fp16.h>
#include <cstdint>

// Problem constants
#define B_ 4
#define S_ 2048
#define D_ 1024

// Scratch (device globals: allocation-free per harness rules)
__device__ __half g_qh [B_ * S_ * D_];            // 16 MB  q in fp16
__device__ __half g_WqT[D_ * D_];                 // 2 MB   Wq^T fp16
__device__ __half g_WvT[D_ * D_];                 // 2 MB   Wv^T fp16
__device__ __half g_WQ [B_ * S_ * D_];            // 16 MB
__device__ __half g_WKV[B_ * S_ * D_];            // 16 MB
__device__ __half g_WKVt[B_ * S_ * D_];           // 16 MB  WKV^T per batch
__device__ __half g_scores[(size_t)B_ * S_ * S_]; // 32 MB  scores -> attn in place

// ---------------------------------------------------------------------------
// Helpers
// ---------------------------------------------------------------------------
__device__ __forceinline__ uint32_t smem_u32(const void* p) {
    uint32_t a;
    asm("{ .reg .u64 t; cvta.to.shared.u64 t, %1; cvt.u32.u64 %0, t; }" : "=r"(a) : "l"(p));
    return a;
}

__device__ __forceinline__ void mma_f16(float* c, const uint32_t* a, const uint32_t* b) {
    asm volatile(
        "mma.sync.aligned.m16n8k16.row.col.f32.f16.f16.f32 "
        "{%0,%1,%2,%3}, {%4,%5,%6,%7}, {%8,%9}, {%0,%1,%2,%3};"
        : "+f"(c[0]), "+f"(c[1]), "+f"(c[2]), "+f"(c[3])
        : "r"(a[0]), "r"(a[1]), "r"(a[2]), "r"(a[3]),
          "r"(b[0]), "r"(b[1]));
}

#define LDMX4(r0, r1, r2, r3, addr) \
    asm volatile("ldmatrix.sync.aligned.m8n8.x4.shared.b16 {%0,%1,%2,%3}, [%4];" \
        : "=r"(r0), "=r"(r1), "=r"(r2), "=r"(r3) : "r"(addr))

#define CP_ASYNC16(dst_u32, src_ptr) \
    asm volatile("cp.async.cg.shared.global [%0], [%1], 16;" \
        :: "r"(dst_u32), "l"(src_ptr) : "memory")
#define CP_COMMIT() asm volatile("cp.async.commit_group;" ::: "memory")
#define CP_WAIT1()  asm volatile("cp.async.wait_group 1;"  ::: "memory")

// ---------------------------------------------------------------------------
// FP16 pipelined GEMM: C = scale * A[M,K] @ B^T, B given as [N,K] (k-contig),
// both operands __half, fp32 accumulate. CTA tile 256x128, KC=64, 3 stages.
// Smem rows are 128B with XOR-16B-chunk swizzle: conflict-free cp.async + ldmatrix.
// CAUSAL: skip tiles with bn > 2*bm+1. LIMITK: K truncated at (bm+1)*256.
// OUT_HALF: write __half (intermediates) else float (final output).
// ---------------------------------------------------------------------------
#define BM 256
#define BN 128
#define KC 64
#define A_STAGE (BM * 128)            // 32 KB
#define B_STAGE (BN * 128)            // 16 KB
#define B_OFF   (3 * A_STAGE)         // 98304
#define SMEM_TOTAL (3 * (A_STAGE + B_STAGE))  // 147456

template <bool CAUSAL, bool LIMITK, bool OUT_HALF>
__global__ void __launch_bounds__(512, 1)
gemm_h(const __half* __restrict__ A, const __half* __restrict__ Bn,
       void* __restrict__ Cv,
       int K, int lda, int ldb, int ldc, float scale,
       size_t aBatch, size_t bBatch, size_t cBatch)
{
    const int bm = blockIdx.y;
    const int bn = blockIdx.x;
    if (CAUSAL && bn > 2 * bm + 1) return;   // whole CTA exits, no barriers yet

    extern __shared__ __align__(128) char smem[];
    const uint32_t sbase = smem_u32(smem);

    const int tid  = threadIdx.x;
    const int warp = tid >> 5;
    const int lane = tid & 31;
    const int wm = (warp >> 2) * 64;   // 4 warp-rows
    const int wn = (warp & 3) * 32;    // 4 warp-cols
    const int g  = lane >> 2;
    const int tq = lane & 3;

    const __half* Ab = A + aBatch * blockIdx.z + (size_t)(bm * BM) * lda;
    const __half* Bb = Bn + bBatch * blockIdx.z + (size_t)(bn * BN) * ldb;

    const int kEnd = LIMITK ? min(K, (bm + 1) * BM) : K;
    const int nc = kEnd / KC;

    float acc[4][4][4] = {};

    // ---- stage loader: 16B granules, swizzled dst ----
    auto issue_stage = [&](int c) {
        if (c < nc) {
            const int s = c % 3;
            const int k0 = c * KC;
            const uint32_t da = sbase + s * A_STAGE;
            const uint32_t db = sbase + B_OFF + s * B_STAGE;
            #pragma unroll
            for (int i = 0; i < 4; i++) {           // A: 2048 granules
                const int gid = tid + i * 512;
                const int row = gid >> 3, ch = gid & 7;
                CP_ASYNC16(da + row * 128 + ((ch ^ (row & 7)) << 4),
                           Ab + (size_t)row * lda + k0 + ch * 8);
            }
            #pragma unroll
            for (int i = 0; i < 2; i++) {           // B: 1024 granules
                const int gid = tid + i * 512;
                const int row = gid >> 3, ch = gid & 7;
                CP_ASYNC16(db + row * 128 + ((ch ^ (row & 7)) << 4),
                           Bb + (size_t)row * ldb + k0 + ch * 8);
            }
        }
        CP_COMMIT();
    };

    issue_stage(0);
    issue_stage(1);

    // per-lane ldmatrix address invariants
    const int l15  = lane & 15;
    const int lhi  = lane >> 4;          // 0/1 -> +8 on k (A)
    const int sx   = lane & 7;           // swizzle xor
    const int bkb  = (lane >> 3) & 1;    // 0/1 -> +8 on k (B)
    const int bRowOfs = ((lane >> 4) << 3) + (lane & 7);  // row within B x4 group

    for (int c = 0; c < nc; c++) {
        CP_WAIT1();
        __syncthreads();
        issue_stage(c + 2);

        const int s = c % 3;
        const uint32_t aRow = sbase + s * A_STAGE + (wm + l15) * 128;
        const uint32_t bRow = sbase + B_OFF + s * B_STAGE + (wn + bRowOfs) * 128;

        #pragma unroll
        for (int ks = 0; ks < 4; ks++) {
            uint32_t af[4][4];
            #pragma unroll
            for (int mi = 0; mi < 4; mi++) {
                const uint32_t addr = aRow + mi * (16 * 128) + (((2 * ks + lhi) ^ sx) << 4);
                LDMX4(af[mi][0], af[mi][1], af[mi][2], af[mi][3], addr);
            }
            uint32_t bf[4][2];
            #pragma unroll
            for (int nip = 0; nip < 2; nip++) {
                const uint32_t addr = bRow + nip * (16 * 128) + (((2 * ks + bkb) ^ sx) << 4);
                LDMX4(bf[2 * nip][0], bf[2 * nip][1], bf[2 * nip + 1][0], bf[2 * nip + 1][1], addr);
            }
            #pragma unroll
            for (int mi = 0; mi < 4; mi++)
                #pragma unroll
                for (int ni = 0; ni < 4; ni++)
                    mma_f16(acc[mi][ni], af[mi], bf[ni]);
        }
    }

    // ---- epilogue ----
    #pragma unroll
    for (int mi = 0; mi < 4; mi++) {
        #pragma unroll
        for (int ni = 0; ni < 4; ni++) {
            const int row0 = bm * BM + wm + mi * 16 + g;
            const int col  = bn * BN + wn + ni * 8 + tq * 2;
            const float v0 = acc[mi][ni][0] * scale, v1 = acc[mi][ni][1] * scale;
            const float v2 = acc[mi][ni][2] * scale, v3 = acc[mi][ni][3] * scale;
            if (OUT_HALF) {
                __half* Cb = (__half*)Cv + cBatch * blockIdx.z;
                *reinterpret_cast<__half2*>(&Cb[(size_t)row0 * ldc + col]) =
                    __floats2half2_rn(v0, v1);
                *reinterpret_cast<__half2*>(&Cb[(size_t)(row0 + 8) * ldc + col]) =
                    __floats2half2_rn(v2, v3);
            } else {
                float* Cb = (float*)Cv + cBatch * blockIdx.z;
                *reinterpret_cast<float2*>(&Cb[(size_t)row0 * ldc + col]) = make_float2(v0, v1);
                *reinterpret_cast<float2*>(&Cb[(size_t)(row0 + 8) * ldc + col]) = make_float2(v2, v3);
            }
        }
    }
}

// ---------------------------------------------------------------------------
// Prepass: fp32 -> fp16 copy, vectorized
// ---------------------------------------------------------------------------
__global__ void __launch_bounds__(256) f32_to_h(const float4* __restrict__ src,
                                                uint2* __restrict__ dst, int n4)
{
    const int i = blockIdx.x * 256 + threadIdx.x;
    if (i < n4) {
        const float4 v = src[i];
        const __half2 h0 = __floats2half2_rn(v.x, v.y);
        const __half2 h1 = __floats2half2_rn(v.z, v.w);
        uint2 u;
        u.x = *reinterpret_cast<const uint32_t*>(&h0);
        u.y = *reinterpret_cast<const uint32_t*>(&h1);
        dst[i] = u;
    }
}

// ---------------------------------------------------------------------------
// Tiled transpose: fp32 src -> fp16 dst, and fp16 src -> fp16 dst (batched z)
// ---------------------------------------------------------------------------
__global__ void __launch_bounds__(256) transpose_f2h(const float* __restrict__ src,
                                                     __half* __restrict__ dst,
                                                     int R, int C)
{
    __shared__ float t[32][33];
    int x = blockIdx.x * 32 + threadIdx.x;
    int y = blockIdx.y * 32 + threadIdx.y;
    #pragma unroll
    for (int j = 0; j < 32; j += 8)
        t[threadIdx.y + j][threadIdx.x] = src[(size_t)(y + j) * C + x];
    __syncthreads();
    x = blockIdx.y * 32 + threadIdx.x;
    y = blockIdx.x * 32 + threadIdx.y;
    #pragma unroll
    for (int j = 0; j < 32; j += 8)
        dst[(size_t)(y + j) * R + x] = __float2half_rn(t[threadIdx.x][threadIdx.y + j]);
}

__global__ void __launch_bounds__(256) transpose_h2h(const __half* __restrict__ src,
                                                     __half* __restrict__ dst,
                                                     int R, int C)
{
    __shared__ float t[32][33];
    const size_t bofs = (size_t)blockIdx.z * R * C;
    src += bofs; dst += bofs;
    int x = blockIdx.x * 32 + threadIdx.x;
    int y = blockIdx.y * 32 + threadIdx.y;
    #pragma unroll
    for (int j = 0; j < 32; j += 8)
        t[threadIdx.y + j][threadIdx.x] = __half2float(src[(size_t)(y + j) * C + x]);
    __syncthreads();
    x = blockIdx.y * 32 + threadIdx.x;
    y = blockIdx.x * 32 + threadIdx.y;
    #pragma unroll
    for (int j = 0; j < 32; j += 8)
        dst[(size_t)(y + j) * R + x] = __float2half_rn(t[threadIdx.x][threadIdx.y + j]);
}

// ---------------------------------------------------------------------------
// Causal row softmax on fp16 scores (fp32 math). Zero-fills to 256-boundary
// so the out-GEMM's truncated K loop reads exact zeros.
// ---------------------------------------------------------------------------
__global__ void __launch_bounds__(256) softmax_h(__half* __restrict__ scores)
{
    __shared__ float red[8];
    __shared__ float bcast;

    const int q = blockIdx.x;
    __half* row = scores + ((size_t)blockIdx.y * S_ + q) * S_;
    const int len = q + 1;
    const int tid = threadIdx.x;

    float m = -3.4e38f;
    for (int i = tid; i < len; i += 256) m = fmaxf(m, __half2float(row[i]));
    #pragma unroll
    for (int o = 16; o; o >>= 1) m = fmaxf(m, __shfl_xor_sync(0xffffffffu, m, o));
    if ((tid & 31) == 0) red[tid >> 5] = m;
    __syncthreads();
    if (tid == 0) {
        float v = red[0];
        #pragma unroll
        for (int i = 1; i < 8; i++) v = fmaxf(v, red[i]);
        bcast = v;
    }
    __syncthreads();
    m = bcast;

    float sum = 0.f;
    for (int i = tid; i < len; i += 256) sum += __expf(__half2float(row[i]) - m);
    #pragma unroll
    for (int o = 16; o; o >>= 1) sum += __shfl_xor_sync(0xffffffffu, sum, o);
    __syncthreads();
    if ((tid & 31) == 0) red[tid >> 5] = sum;
    __syncthreads();
    if (tid == 0) {
        float v = 0.f;
        #pragma unroll
        for (int i = 0; i < 8; i++) v += red[i];
        bcast = 1.f / v;
    }
    __syncthreads();
    const float inv = bcast;

    const int tileEnd = ((q >> 8) + 1) << 8;   // end of the 256-row K-block
    for (int i = tid; i < tileEnd; i += 256)
        row[i] = (i < len) ? __float2half_rn(__expf(__half2float(row[i]) - m) * inv)
                           : __half(0.f);
}

// ---------------------------------------------------------------------------
// Launch
// ---------------------------------------------------------------------------
extern "C" void kernel_launch(void* const* d_in, const int* in_sizes, int n_in,
                              void* d_out, int out_size)
{
    (void)in_sizes; (void)n_in; (void)out_size;
    const float* q  = (const float*)d_in[0];
    const float* Wq = (const float*)d_in[1];
    // d_in[2] = Wk (unused by reference), d_in[4] = mask (causal, analytic)
    const float* Wv = (const float*)d_in[3];
    float* out = (float*)d_out;

    __half *pq, *pWqT, *pWvT, *pWQ, *pWKV, *pWKVt, *pS;
    cudaGetSymbolAddress((void**)&pq,    g_qh);
    cudaGetSymbolAddress((void**)&pWqT,  g_WqT);
    cudaGetSymbolAddress((void**)&pWvT,  g_WvT);
    cudaGetSymbolAddress((void**)&pWQ,   g_WQ);
    cudaGetSymbolAddress((void**)&pWKV,  g_WKV);
    cudaGetSymbolAddress((void**)&pWKVt, g_WKVt);
    cudaGetSymbolAddress((void**)&pS,    g_scores);

    cudaFuncSetAttribute(gemm_h<false, false, true>,
                         cudaFuncAttributeMaxDynamicSharedMemorySize, SMEM_TOTAL);
    cudaFuncSetAttribute(gemm_h<true, false, true>,
                         cudaFuncAttributeMaxDynamicSharedMemorySize, SMEM_TOTAL);
    cudaFuncSetAttribute(gemm_h<false, true, false>,
                         cudaFuncAttributeMaxDynamicSharedMemorySize, SMEM_TOTAL);

    // 0) Prepass: q -> half; Wq, Wv transpose -> half
    f32_to_h<<<(B_ * S_ * D_ / 4 + 255) / 256, 256>>>(
        (const float4*)q, (uint2*)pq, B_ * S_ * D_ / 4);
    {
        const dim3 tgrid(D_ / 32, D_ / 32, 1);
        const dim3 tblk(32, 8);
        transpose_f2h<<<tgrid, tblk>>>(Wq, pWqT, D_, D_);
        transpose_f2h<<<tgrid, tblk>>>(Wv, pWvT, D_, D_);
    }

    // 1) Projections: WQ = q@Wq, WKV = q@Wv  (B as [N,K]); outputs fp16
    {
        const dim3 grid(D_ / BN, (B_ * S_) / BM, 1);
        gemm_h<false, false, true><<<grid, 512, SMEM_TOTAL>>>(
            pq, pWqT, pWQ, D_, D_, D_, D_, 1.0f, 0, 0, 0);
        gemm_h<false, false, true><<<grid, 512, SMEM_TOTAL>>>(
            pq, pWvT, pWKV, D_, D_, D_, D_, 1.0f, 0, 0, 0);
    }

    // 1b) Transpose WKV per batch: [S,D] -> [D,S]
    {
        const dim3 tgrid(D_ / 32, S_ / 32, B_);
        const dim3 tblk(32, 8);
        transpose_h2h<<<tgrid, tblk>>>(pWKV, pWKVt, S_, D_);
    }

    // 2) Scores = WQ @ WKV^T / 32, causal tiles only (fp16 out)
    {
        const dim3 grid(S_ / BN, S_ / BM, B_);
        gemm_h<true, false, true><<<grid, 512, SMEM_TOTAL>>>(
            pWQ, pWKV, pS, D_, D_, D_, S_, 1.0f / 32.0f,
            (size_t)S_ * D_, (size_t)S_ * D_, (size_t)S_ * S_);
    }

    // 3) Causal softmax in place (fp16)
    {
        const dim3 grid(S_, B_);
        softmax_h<<<grid, 256>>>(pS);
    }

    // 4) out = attn @ WKV (B = WKV^T as [N=D, K=S]); K truncated causally; fp32 out
    {
        const dim3 grid(D_ / BN, S_ / BM, B_);
        gemm_h<false, true, false><<<grid, 512, SMEM_TOTAL>>>(
            pS, pWKVt, out, S_, S_, S_, D_, 1.0f,
            (size_t)S_ * S_, (size_t)S_ * D_, (size_t)S_ * D_);
    }
}

// round 5
// speedup vs baseline: 3.5093x; 1.0099x over previous
#include <cuda_runtime.h>
#include <cuda_fp16.h>
#include <cstdint>

// Problem constants
#define B_ 4
#define S_ 2048
#define D_ 1024

// Scratch (device globals: allocation-free per harness rules)
__device__ __half g_qh [B_ * S_ * D_];            // 16 MB  q in fp16
__device__ __half g_WT [2 * D_ * D_];             // 4 MB   [WqT ; WvT] as [2048,1024]
__device__ __half g_QKV[(size_t)B_ * S_ * 2 * D_];// 32 MB  [8192, 2048]: WQ | WKV
__device__ __half g_WKVt[B_ * S_ * D_];           // 16 MB  WKV^T per batch [D, S]
__device__ __half g_scores[(size_t)B_ * S_ * S_]; // 32 MB  scores -> attn in place

// ---------------------------------------------------------------------------
// Helpers
// ---------------------------------------------------------------------------
__device__ __forceinline__ uint32_t smem_u32(const void* p) {
    uint32_t a;
    asm("{ .reg .u64 t; cvta.to.shared.u64 t, %1; cvt.u32.u64 %0, t; }" : "=r"(a) : "l"(p));
    return a;
}

__device__ __forceinline__ void mma_f16(float* c, const uint32_t* a, const uint32_t* b) {
    asm volatile(
        "mma.sync.aligned.m16n8k16.row.col.f32.f16.f16.f32 "
        "{%0,%1,%2,%3}, {%4,%5,%6,%7}, {%8,%9}, {%0,%1,%2,%3};"
        : "+f"(c[0]), "+f"(c[1]), "+f"(c[2]), "+f"(c[3])
        : "r"(a[0]), "r"(a[1]), "r"(a[2]), "r"(a[3]),
          "r"(b[0]), "r"(b[1]));
}

#define LDMX4(r0, r1, r2, r3, addr) \
    asm volatile("ldmatrix.sync.aligned.m8n8.x4.shared.b16 {%0,%1,%2,%3}, [%4];" \
        : "=r"(r0), "=r"(r1), "=r"(r2), "=r"(r3) : "r"(addr))

#define CP_ASYNC16(dst_u32, src_ptr) \
    asm volatile("cp.async.cg.shared.global [%0], [%1], 16;" \
        :: "r"(dst_u32), "l"(src_ptr) : "memory")
#define CP_COMMIT() asm volatile("cp.async.commit_group;" ::: "memory")
#define CP_WAIT1()  asm volatile("cp.async.wait_group 1;"  ::: "memory")

// ---------------------------------------------------------------------------
// FP16 pipelined GEMM: C = scale * A[M,K] @ B^T, B given as [N,K] (k-contig),
// fp32 accumulate. CTA tile 256x128, 8 warps (64x64 warp tile), KC=64, 3-stage
// cp.async ring, register double-buffered ldmatrix fragments.
// Smem rows 128B, XOR-16B-chunk swizzle (conflict-free cp.async + ldmatrix).
// CAUSAL: skip tiles with bn > 2*bm+1. LIMITK: K truncated at (bm+1)*256.
// OUT_HALF: write __half (intermediates) else float (final output).
// ---------------------------------------------------------------------------
#define BM 256
#define BN 128
#define KC 64
#define A_STAGE (BM * 128)            // 32 KB
#define B_STAGE (BN * 128)            // 16 KB
#define B_OFF   (3 * A_STAGE)         // 98304
#define SMEM_TOTAL (3 * (A_STAGE + B_STAGE))  // 147456

template <bool CAUSAL, bool LIMITK, bool OUT_HALF>
__global__ void __launch_bounds__(256, 1)
gemm_h(const __half* __restrict__ A, const __half* __restrict__ Bn,
       void* __restrict__ Cv,
       int K, int lda, int ldb, int ldc, float scale,
       size_t aBatch, size_t bBatch, size_t cBatch)
{
    const int bm = blockIdx.y;
    const int bn = blockIdx.x;
    if (CAUSAL && bn > 2 * bm + 1) return;   // whole CTA exits, no barriers yet

    extern __shared__ __align__(128) char smem[];
    const uint32_t sbase = smem_u32(smem);

    const int tid  = threadIdx.x;
    const int warp = tid >> 5;
    const int lane = tid & 31;
    const int wm = (warp >> 1) * 64;   // 4 warp-rows of 64
    const int wn = (warp & 1) * 64;    // 2 warp-cols of 64
    const int g  = lane >> 2;
    const int tq = lane & 3;

    const __half* Ab = A + aBatch * blockIdx.z + (size_t)(bm * BM) * lda;
    const __half* Bb = Bn + bBatch * blockIdx.z + (size_t)(bn * BN) * ldb;

    const int kEnd = LIMITK ? min(K, (bm + 1) * BM) : K;
    const int nc = kEnd / KC;

    float acc[4][8][4] = {};

    // ---- stage loader: 16B granules, swizzled dst ----
    auto issue_stage = [&](int c) {
        if (c < nc) {
            const int s = c % 3;
            const int k0 = c * KC;
            const uint32_t da = sbase + s * A_STAGE;
            const uint32_t db = sbase + B_OFF + s * B_STAGE;
            #pragma unroll
            for (int i = 0; i < 8; i++) {           // A: 2048 granules
                const int gid = tid + i * 256;
                const int row = gid >> 3, ch = gid & 7;
                CP_ASYNC16(da + row * 128 + ((ch ^ (row & 7)) << 4),
                           Ab + (size_t)row * lda + k0 + ch * 8);
            }
            #pragma unroll
            for (int i = 0; i < 4; i++) {           // B: 1024 granules
                const int gid = tid + i * 256;
                const int row = gid >> 3, ch = gid & 7;
                CP_ASYNC16(db + row * 128 + ((ch ^ (row & 7)) << 4),
                           Bb + (size_t)row * ldb + k0 + ch * 8);
            }
        }
        CP_COMMIT();
    };

    issue_stage(0);
    issue_stage(1);

    // per-lane ldmatrix address invariants (patterns proven in round 4)
    const int l15  = lane & 15;
    const int lhi  = lane >> 4;          // A: k half select
    const int sx   = lane & 7;           // swizzle xor
    const int bkb  = (lane >> 3) & 1;    // B: k half select
    const int bRowOfs = ((lane >> 4) << 3) + (lane & 7);  // B: row within x4 group

    uint32_t af[2][4][4];
    uint32_t bf[2][8][2];

    for (int c = 0; c < nc; c++) {
        CP_WAIT1();
        __syncthreads();
        issue_stage(c + 2);

        const int s = c % 3;
        const uint32_t aRow = sbase + s * A_STAGE + (wm + l15) * 128;
        const uint32_t bRow = sbase + B_OFF + s * B_STAGE + (wn + bRowOfs) * 128;

        // fragment loader for one k16 step into buffer `bu`
        auto load_frags = [&](int ks, int bu) {
            #pragma unroll
            for (int mi = 0; mi < 4; mi++) {
                const uint32_t addr = aRow + mi * (16 * 128) + (((2 * ks + lhi) ^ sx) << 4);
                LDMX4(af[bu][mi][0], af[bu][mi][1], af[bu][mi][2], af[bu][mi][3], addr);
            }
            #pragma unroll
            for (int nq = 0; nq < 4; nq++) {
                const uint32_t addr = bRow + nq * (16 * 128) + (((2 * ks + bkb) ^ sx) << 4);
                LDMX4(bf[bu][2 * nq][0], bf[bu][2 * nq][1],
                      bf[bu][2 * nq + 1][0], bf[bu][2 * nq + 1][1], addr);
            }
        };

        load_frags(0, 0);
        #pragma unroll
        for (int ks = 0; ks < 4; ks++) {
            const int bu = ks & 1;
            if (ks < 3) load_frags(ks + 1, bu ^ 1);
            #pragma unroll
            for (int mi = 0; mi < 4; mi++)
                #pragma unroll
                for (int ni = 0; ni < 8; ni++)
                    mma_f16(acc[mi][ni], af[bu][mi], bf[bu][ni]);
        }
    }

    // ---- epilogue ----
    #pragma unroll
    for (int mi = 0; mi < 4; mi++) {
        #pragma unroll
        for (int ni = 0; ni < 8; ni++) {
            const int row0 = bm * BM + wm + mi * 16 + g;
            const int col  = bn * BN + wn + ni * 8 + tq * 2;
            const float v0 = acc[mi][ni][0] * scale, v1 = acc[mi][ni][1] * scale;
            const float v2 = acc[mi][ni][2] * scale, v3 = acc[mi][ni][3] * scale;
            if (OUT_HALF) {
                __half* Cb = (__half*)Cv + cBatch * blockIdx.z;
                *reinterpret_cast<__half2*>(&Cb[(size_t)row0 * ldc + col]) =
                    __floats2half2_rn(v0, v1);
                *reinterpret_cast<__half2*>(&Cb[(size_t)(row0 + 8) * ldc + col]) =
                    __floats2half2_rn(v2, v3);
            } else {
                float* Cb = (float*)Cv + cBatch * blockIdx.z;
                *reinterpret_cast<float2*>(&Cb[(size_t)row0 * ldc + col]) = make_float2(v0, v1);
                *reinterpret_cast<float2*>(&Cb[(size_t)(row0 + 8) * ldc + col]) = make_float2(v2, v3);
            }
        }
    }
}

// ---------------------------------------------------------------------------
// Prepass: fp32 -> fp16 copy, vectorized
// ---------------------------------------------------------------------------
__global__ void __launch_bounds__(256) f32_to_h(const float4* __restrict__ src,
                                                uint2* __restrict__ dst, int n4)
{
    const int i = blockIdx.x * 256 + threadIdx.x;
    if (i < n4) {
        const float4 v = src[i];
        const __half2 h0 = __floats2half2_rn(v.x, v.y);
        const __half2 h1 = __floats2half2_rn(v.z, v.w);
        uint2 u;
        u.x = *reinterpret_cast<const uint32_t*>(&h0);
        u.y = *reinterpret_cast<const uint32_t*>(&h1);
        dst[i] = u;
    }
}

// ---------------------------------------------------------------------------
// Tiled transposes
// ---------------------------------------------------------------------------
__global__ void __launch_bounds__(256) transpose_f2h(const float* __restrict__ src,
                                                     __half* __restrict__ dst,
                                                     int R, int C)
{
    __shared__ float t[32][33];
    int x = blockIdx.x * 32 + threadIdx.x;
    int y = blockIdx.y * 32 + threadIdx.y;
    #pragma unroll
    for (int j = 0; j < 32; j += 8)
        t[threadIdx.y + j][threadIdx.x] = src[(size_t)(y + j) * C + x];
    __syncthreads();
    x = blockIdx.y * 32 + threadIdx.x;
    y = blockIdx.x * 32 + threadIdx.y;
    #pragma unroll
    for (int j = 0; j < 32; j += 8)
        dst[(size_t)(y + j) * R + x] = __float2half_rn(t[threadIdx.x][threadIdx.y + j]);
}

// src [R x C] with row stride srcLd -> dst [C x R] with row stride dstLd, batched
__global__ void __launch_bounds__(256) transpose_h2h(const __half* __restrict__ src,
                                                     __half* __restrict__ dst,
                                                     int R, int C, int srcLd, int dstLd,
                                                     size_t srcBatch, size_t dstBatch)
{
    __shared__ float t[32][33];
    src += srcBatch * blockIdx.z;
    dst += dstBatch * blockIdx.z;
    int x = blockIdx.x * 32 + threadIdx.x;
    int y = blockIdx.y * 32 + threadIdx.y;
    #pragma unroll
    for (int j = 0; j < 32; j += 8)
        t[threadIdx.y + j][threadIdx.x] = __half2float(src[(size_t)(y + j) * srcLd + x]);
    __syncthreads();
    x = blockIdx.y * 32 + threadIdx.x;
    y = blockIdx.x * 32 + threadIdx.y;
    #pragma unroll
    for (int j = 0; j < 32; j += 8)
        dst[(size_t)(y + j) * dstLd + x] = __float2half_rn(t[threadIdx.x][threadIdx.y + j]);
}

// ---------------------------------------------------------------------------
// Causal row softmax on fp16 scores (fp32 math). Zero-fills to 256-boundary
// so the out-GEMM's truncated K loop reads exact zeros.
// ---------------------------------------------------------------------------
__global__ void __launch_bounds__(256) softmax_h(__half* __restrict__ scores)
{
    __shared__ float red[8];
    __shared__ float bcast;

    const int q = blockIdx.x;
    __half* row = scores + ((size_t)blockIdx.y * S_ + q) * S_;
    const int len = q + 1;
    const int tid = threadIdx.x;

    float m = -3.4e38f;
    for (int i = tid; i < len; i += 256) m = fmaxf(m, __half2float(row[i]));
    #pragma unroll
    for (int o = 16; o; o >>= 1) m = fmaxf(m, __shfl_xor_sync(0xffffffffu, m, o));
    if ((tid & 31) == 0) red[tid >> 5] = m;
    __syncthreads();
    if (tid == 0) {
        float v = red[0];
        #pragma unroll
        for (int i = 1; i < 8; i++) v = fmaxf(v, red[i]);
        bcast = v;
    }
    __syncthreads();
    m = bcast;

    float sum = 0.f;
    for (int i = tid; i < len; i += 256) sum += __expf(__half2float(row[i]) - m);
    #pragma unroll
    for (int o = 16; o; o >>= 1) sum += __shfl_xor_sync(0xffffffffu, sum, o);
    __syncthreads();
    if ((tid & 31) == 0) red[tid >> 5] = sum;
    __syncthreads();
    if (tid == 0) {
        float v = 0.f;
        #pragma unroll
        for (int i = 0; i < 8; i++) v += red[i];
        bcast = 1.f / v;
    }
    __syncthreads();
    const float inv = bcast;

    const int tileEnd = ((q >> 8) + 1) << 8;   // end of the 256-row K-block
    for (int i = tid; i < tileEnd; i += 256)
        row[i] = (i < len) ? __float2half_rn(__expf(__half2float(row[i]) - m) * inv)
                           : __half(0.f);
}

// ---------------------------------------------------------------------------
// Launch
// ---------------------------------------------------------------------------
extern "C" void kernel_launch(void* const* d_in, const int* in_sizes, int n_in,
                              void* d_out, int out_size)
{
    (void)in_sizes; (void)n_in; (void)out_size;
    const float* q  = (const float*)d_in[0];
    const float* Wq = (const float*)d_in[1];
    // d_in[2] = Wk (unused by reference), d_in[4] = mask (causal, analytic)
    const float* Wv = (const float*)d_in[3];
    float* out = (float*)d_out;

    __half *pq, *pWT, *pQKV, *pWKVt, *pS;
    cudaGetSymbolAddress((void**)&pq,    g_qh);
    cudaGetSymbolAddress((void**)&pWT,   g_WT);
    cudaGetSymbolAddress((void**)&pQKV,  g_QKV);
    cudaGetSymbolAddress((void**)&pWKVt, g_WKVt);
    cudaGetSymbolAddress((void**)&pS,    g_scores);

    cudaFuncSetAttribute(gemm_h<false, false, true>,
                         cudaFuncAttributeMaxDynamicSharedMemorySize, SMEM_TOTAL);
    cudaFuncSetAttribute(gemm_h<true, false, true>,
                         cudaFuncAttributeMaxDynamicSharedMemorySize, SMEM_TOTAL);
    cudaFuncSetAttribute(gemm_h<false, true, false>,
                         cudaFuncAttributeMaxDynamicSharedMemorySize, SMEM_TOTAL);

    // 0) Prepass: q -> half; Wq, Wv transposed into concatenated [2048,1024] fp16
    f32_to_h<<<(B_ * S_ * D_ / 4 + 255) / 256, 256>>>(
        (const float4*)q, (uint2*)pq, B_ * S_ * D_ / 4);
    {
        const dim3 tgrid(D_ / 32, D_ / 32, 1);
        const dim3 tblk(32, 8);
        transpose_f2h<<<tgrid, tblk>>>(Wq, pWT, D_, D_);
        transpose_f2h<<<tgrid, tblk>>>(Wv, pWT + D_ * D_, D_, D_);
    }

    // 1) Fused projections: QKV[8192,2048] = q @ [Wq | Wv]  (B = [2048,1024])
    {
        const dim3 grid(2 * D_ / BN, (B_ * S_) / BM, 1);
        gemm_h<false, false, true><<<grid, 256, SMEM_TOTAL>>>(
            pq, pWT, pQKV, D_, D_, D_, 2 * D_, 1.0f, 0, 0, 0);
    }

    // 1b) Transpose WKV (= QKV cols 1024..2047) per batch: [S,D] -> [D,S]
    {
        const dim3 tgrid(D_ / 32, S_ / 32, B_);
        const dim3 tblk(32, 8);
        transpose_h2h<<<tgrid, tblk>>>(pQKV + D_, pWKVt, S_, D_, 2 * D_, S_,
                                       (size_t)S_ * 2 * D_, (size_t)D_ * S_);
    }

    // 2) Scores = WQ @ WKV^T / 32, causal tiles only (fp16 out)
    {
        const dim3 grid(S_ / BN, S_ / BM, B_);
        gemm_h<true, false, true><<<grid, 256, SMEM_TOTAL>>>(
            pQKV, pQKV + D_, pS, D_, 2 * D_, 2 * D_, S_, 1.0f / 32.0f,
            (size_t)S_ * 2 * D_, (size_t)S_ * 2 * D_, (size_t)S_ * S_);
    }

    // 3) Causal softmax in place (fp16)
    {
        const dim3 grid(S_, B_);
        softmax_h<<<grid, 256>>>(pS);
    }

    // 4) out = attn @ WKV (B = WKV^T as [N=D, K=S]); K truncated causally; fp32 out
    {
        const dim3 grid(D_ / BN, S_ / BM, B_);
        gemm_h<false, true, false><<<grid, 256, SMEM_TOTAL>>>(
            pS, pWKVt, out, S_, S_, S_, D_, 1.0f,
            (size_t)S_ * S_, (size_t)S_ * D_, (size_t)S_ * D_);
    }
}

// round 6
// speedup vs baseline: 4.0169x; 1.1446x over previous
#include <cuda_runtime.h>
#include <cuda_fp16.h>
#include <cstdint>

// Problem constants
#define B_ 4
#define S_ 2048
#define D_ 1024

// Scratch (device globals: allocation-free per harness rules)
__device__ __half g_qh [B_ * S_ * D_];            // 16 MB  q in fp16
__device__ __half g_WT [2 * D_ * D_];             // 4 MB   [WqT ; WvT] as [2048,1024]
__device__ __half g_QKV[(size_t)B_ * S_ * 2 * D_];// 32 MB  [8192, 2048]: WQ | WKV
__device__ __half g_WKVt[B_ * S_ * D_];           // 16 MB  WKV^T per batch [D, S]
__device__ __half g_scores[(size_t)B_ * S_ * S_]; // 32 MB  scores -> attn in place

// ---------------------------------------------------------------------------
// Helpers
// ---------------------------------------------------------------------------
__device__ __forceinline__ uint32_t smem_u32(const void* p) {
    uint32_t a;
    asm("{ .reg .u64 t; cvta.to.shared.u64 t, %1; cvt.u32.u64 %0, t; }" : "=r"(a) : "l"(p));
    return a;
}

__device__ __forceinline__ void mma_f16(float* c, const uint32_t* a, const uint32_t* b) {
    asm volatile(
        "mma.sync.aligned.m16n8k16.row.col.f32.f16.f16.f32 "
        "{%0,%1,%2,%3}, {%4,%5,%6,%7}, {%8,%9}, {%0,%1,%2,%3};"
        : "+f"(c[0]), "+f"(c[1]), "+f"(c[2]), "+f"(c[3])
        : "r"(a[0]), "r"(a[1]), "r"(a[2]), "r"(a[3]),
          "r"(b[0]), "r"(b[1]));
}

#define LDMX4(r0, r1, r2, r3, addr) \
    asm volatile("ldmatrix.sync.aligned.m8n8.x4.shared.b16 {%0,%1,%2,%3}, [%4];" \
        : "=r"(r0), "=r"(r1), "=r"(r2), "=r"(r3) : "r"(addr))

#define CP_ASYNC16(dst_u32, src_ptr) \
    asm volatile("cp.async.cg.shared.global [%0], [%1], 16;" \
        :: "r"(dst_u32), "l"(src_ptr) : "memory")
#define CP_COMMIT() asm volatile("cp.async.commit_group;" ::: "memory")
#define CP_WAIT1()  asm volatile("cp.async.wait_group 1;"  ::: "memory")

// ---------------------------------------------------------------------------
// FP16 pipelined GEMM: C = scale * A[M,K] @ B^T, B given as [N,K] (k-contig),
// fp32 accumulate. CTA tile 128x128, 4 warps (64x64 warp tile), KC=64,
// 3-stage cp.async ring, register double-buffered ldmatrix fragments,
// 2 CTAs/SM (96KB smem, ~246 regs).
// Smem rows 128B, XOR-16B-chunk swizzle (conflict-free cp.async + ldmatrix).
// CAUSAL: skip tiles with bn > bm. LIMITK: K truncated at (bm+1)*128.
// OUT_HALF: write __half (intermediates) else float (final output).
// ---------------------------------------------------------------------------
#define BM 128
#define BN 128
#define KC 64
#define A_STAGE (BM * 128)            // 16 KB
#define B_STAGE (BN * 128)            // 16 KB
#define B_OFF   (3 * A_STAGE)         // 49152
#define SMEM_TOTAL (3 * (A_STAGE + B_STAGE))  // 98304

template <bool CAUSAL, bool LIMITK, bool OUT_HALF>
__global__ void __launch_bounds__(128, 2)
gemm_h(const __half* __restrict__ A, const __half* __restrict__ Bn,
       void* __restrict__ Cv,
       int K, int lda, int ldb, int ldc, float scale,
       size_t aBatch, size_t bBatch, size_t cBatch)
{
    const int bm = blockIdx.y;
    const int bn = blockIdx.x;
    if (CAUSAL && bn > bm) return;   // whole CTA exits, no barriers yet

    extern __shared__ __align__(128) char smem[];
    const uint32_t sbase = smem_u32(smem);

    const int tid  = threadIdx.x;
    const int warp = tid >> 5;
    const int lane = tid & 31;
    const int wm = (warp >> 1) * 64;   // 2 warp-rows of 64
    const int wn = (warp & 1) * 64;    // 2 warp-cols of 64
    const int g  = lane >> 2;
    const int tq = lane & 3;

    const __half* Ab = A + aBatch * blockIdx.z + (size_t)(bm * BM) * lda;
    const __half* Bb = Bn + bBatch * blockIdx.z + (size_t)(bn * BN) * ldb;

    const int kEnd = LIMITK ? min(K, (bm + 1) * BM) : K;
    const int nc = kEnd / KC;

    float acc[4][8][4] = {};

    // ---- stage loader: 16B granules, swizzled dst (8 A + 8 B per thread) ----
    auto issue_stage = [&](int c) {
        if (c < nc) {
            const int s = c % 3;
            const int k0 = c * KC;
            const uint32_t da = sbase + s * A_STAGE;
            const uint32_t db = sbase + B_OFF + s * B_STAGE;
            #pragma unroll
            for (int i = 0; i < 8; i++) {           // A: 1024 granules
                const int gid = tid + i * 128;
                const int row = gid >> 3, ch = gid & 7;
                CP_ASYNC16(da + row * 128 + ((ch ^ (row & 7)) << 4),
                           Ab + (size_t)row * lda + k0 + ch * 8);
            }
            #pragma unroll
            for (int i = 0; i < 8; i++) {           // B: 1024 granules
                const int gid = tid + i * 128;
                const int row = gid >> 3, ch = gid & 7;
                CP_ASYNC16(db + row * 128 + ((ch ^ (row & 7)) << 4),
                           Bb + (size_t)row * ldb + k0 + ch * 8);
            }
        }
        CP_COMMIT();
    };

    issue_stage(0);
    issue_stage(1);

    // per-lane ldmatrix address invariants (patterns proven in rounds 4-5)
    const int l15  = lane & 15;
    const int lhi  = lane >> 4;          // A: k half select
    const int sx   = lane & 7;           // swizzle xor
    const int bkb  = (lane >> 3) & 1;    // B: k half select
    const int bRowOfs = ((lane >> 4) << 3) + (lane & 7);  // B: row within x4 group

    uint32_t af[2][4][4];
    uint32_t bf[2][8][2];

    for (int c = 0; c < nc; c++) {
        CP_WAIT1();
        __syncthreads();
        issue_stage(c + 2);

        const int s = c % 3;
        const uint32_t aRow = sbase + s * A_STAGE + (wm + l15) * 128;
        const uint32_t bRow = sbase + B_OFF + s * B_STAGE + (wn + bRowOfs) * 128;

        // fragment loader for one k16 step into buffer `bu`
        auto load_frags = [&](int ks, int bu) {
            #pragma unroll
            for (int mi = 0; mi < 4; mi++) {
                const uint32_t addr = aRow + mi * (16 * 128) + (((2 * ks + lhi) ^ sx) << 4);
                LDMX4(af[bu][mi][0], af[bu][mi][1], af[bu][mi][2], af[bu][mi][3], addr);
            }
            #pragma unroll
            for (int nq = 0; nq < 4; nq++) {
                const uint32_t addr = bRow + nq * (16 * 128) + (((2 * ks + bkb) ^ sx) << 4);
                LDMX4(bf[bu][2 * nq][0], bf[bu][2 * nq][1],
                      bf[bu][2 * nq + 1][0], bf[bu][2 * nq + 1][1], addr);
            }
        };

        load_frags(0, 0);
        #pragma unroll
        for (int ks = 0; ks < 4; ks++) {
            const int bu = ks & 1;
            if (ks < 3) load_frags(ks + 1, bu ^ 1);
            #pragma unroll
            for (int mi = 0; mi < 4; mi++)
                #pragma unroll
                for (int ni = 0; ni < 8; ni++)
                    mma_f16(acc[mi][ni], af[bu][mi], bf[bu][ni]);
        }
    }

    // ---- epilogue ----
    #pragma unroll
    for (int mi = 0; mi < 4; mi++) {
        #pragma unroll
        for (int ni = 0; ni < 8; ni++) {
            const int row0 = bm * BM + wm + mi * 16 + g;
            const int col  = bn * BN + wn + ni * 8 + tq * 2;
            const float v0 = acc[mi][ni][0] * scale, v1 = acc[mi][ni][1] * scale;
            const float v2 = acc[mi][ni][2] * scale, v3 = acc[mi][ni][3] * scale;
            if (OUT_HALF) {
                __half* Cb = (__half*)Cv + cBatch * blockIdx.z;
                *reinterpret_cast<__half2*>(&Cb[(size_t)row0 * ldc + col]) =
                    __floats2half2_rn(v0, v1);
                *reinterpret_cast<__half2*>(&Cb[(size_t)(row0 + 8) * ldc + col]) =
                    __floats2half2_rn(v2, v3);
            } else {
                float* Cb = (float*)Cv + cBatch * blockIdx.z;
                *reinterpret_cast<float2*>(&Cb[(size_t)row0 * ldc + col]) = make_float2(v0, v1);
                *reinterpret_cast<float2*>(&Cb[(size_t)(row0 + 8) * ldc + col]) = make_float2(v2, v3);
            }
        }
    }
}

// ---------------------------------------------------------------------------
// Prepass: fp32 -> fp16 copy, vectorized
// ---------------------------------------------------------------------------
__global__ void __launch_bounds__(256) f32_to_h(const float4* __restrict__ src,
                                                uint2* __restrict__ dst, int n4)
{
    const int i = blockIdx.x * 256 + threadIdx.x;
    if (i < n4) {
        const float4 v = src[i];
        const __half2 h0 = __floats2half2_rn(v.x, v.y);
        const __half2 h1 = __floats2half2_rn(v.z, v.w);
        uint2 u;
        u.x = *reinterpret_cast<const uint32_t*>(&h0);
        u.y = *reinterpret_cast<const uint32_t*>(&h1);
        dst[i] = u;
    }
}

// ---------------------------------------------------------------------------
// Tiled transposes
// ---------------------------------------------------------------------------
__global__ void __launch_bounds__(256) transpose_f2h(const float* __restrict__ src,
                                                     __half* __restrict__ dst,
                                                     int R, int C)
{
    __shared__ float t[32][33];
    int x = blockIdx.x * 32 + threadIdx.x;
    int y = blockIdx.y * 32 + threadIdx.y;
    #pragma unroll
    for (int j = 0; j < 32; j += 8)
        t[threadIdx.y + j][threadIdx.x] = src[(size_t)(y + j) * C + x];
    __syncthreads();
    x = blockIdx.y * 32 + threadIdx.x;
    y = blockIdx.x * 32 + threadIdx.y;
    #pragma unroll
    for (int j = 0; j < 32; j += 8)
        dst[(size_t)(y + j) * R + x] = __float2half_rn(t[threadIdx.x][threadIdx.y + j]);
}

// src [R x C] with row stride srcLd -> dst [C x R] with row stride dstLd, batched
__global__ void __launch_bounds__(256) transpose_h2h(const __half* __restrict__ src,
                                                     __half* __restrict__ dst,
                                                     int R, int C, int srcLd, int dstLd,
                                                     size_t srcBatch, size_t dstBatch)
{
    __shared__ float t[32][33];
    src += srcBatch * blockIdx.z;
    dst += dstBatch * blockIdx.z;
    int x = blockIdx.x * 32 + threadIdx.x;
    int y = blockIdx.y * 32 + threadIdx.y;
    #pragma unroll
    for (int j = 0; j < 32; j += 8)
        t[threadIdx.y + j][threadIdx.x] = __half2float(src[(size_t)(y + j) * srcLd + x]);
    __syncthreads();
    x = blockIdx.y * 32 + threadIdx.x;
    y = blockIdx.x * 32 + threadIdx.y;
    #pragma unroll
    for (int j = 0; j < 32; j += 8)
        dst[(size_t)(y + j) * dstLd + x] = __float2half_rn(t[threadIdx.x][threadIdx.y + j]);
}

// ---------------------------------------------------------------------------
// Causal row softmax on fp16 scores (fp32 math). Zero-fills to 128-boundary
// so the out-GEMM's truncated K loop reads exact zeros.
// ---------------------------------------------------------------------------
__global__ void __launch_bounds__(256) softmax_h(__half* __restrict__ scores)
{
    __shared__ float red[8];
    __shared__ float bcast;

    const int q = blockIdx.x;
    __half* row = scores + ((size_t)blockIdx.y * S_ + q) * S_;
    const int len = q + 1;
    const int tid = threadIdx.x;

    float m = -3.4e38f;
    for (int i = tid; i < len; i += 256) m = fmaxf(m, __half2float(row[i]));
    #pragma unroll
    for (int o = 16; o; o >>= 1) m = fmaxf(m, __shfl_xor_sync(0xffffffffu, m, o));
    if ((tid & 31) == 0) red[tid >> 5] = m;
    __syncthreads();
    if (tid == 0) {
        float v = red[0];
        #pragma unroll
        for (int i = 1; i < 8; i++) v = fmaxf(v, red[i]);
        bcast = v;
    }
    __syncthreads();
    m = bcast;

    float sum = 0.f;
    for (int i = tid; i < len; i += 256) sum += __expf(__half2float(row[i]) - m);
    #pragma unroll
    for (int o = 16; o; o >>= 1) sum += __shfl_xor_sync(0xffffffffu, sum, o);
    __syncthreads();
    if ((tid & 31) == 0) red[tid >> 5] = sum;
    __syncthreads();
    if (tid == 0) {
        float v = 0.f;
        #pragma unroll
        for (int i = 0; i < 8; i++) v += red[i];
        bcast = 1.f / v;
    }
    __syncthreads();
    const float inv = bcast;

    const int tileEnd = ((q >> 7) + 1) << 7;   // end of the 128-row K-block
    for (int i = tid; i < tileEnd; i += 256)
        row[i] = (i < len) ? __float2half_rn(__expf(__half2float(row[i]) - m) * inv)
                           : __half(0.f);
}

// ---------------------------------------------------------------------------
// Launch
// ---------------------------------------------------------------------------
extern "C" void kernel_launch(void* const* d_in, const int* in_sizes, int n_in,
                              void* d_out, int out_size)
{
    (void)in_sizes; (void)n_in; (void)out_size;
    const float* q  = (const float*)d_in[0];
    const float* Wq = (const float*)d_in[1];
    // d_in[2] = Wk (unused by reference), d_in[4] = mask (causal, analytic)
    const float* Wv = (const float*)d_in[3];
    float* out = (float*)d_out;

    __half *pq, *pWT, *pQKV, *pWKVt, *pS;
    cudaGetSymbolAddress((void**)&pq,    g_qh);
    cudaGetSymbolAddress((void**)&pWT,   g_WT);
    cudaGetSymbolAddress((void**)&pQKV,  g_QKV);
    cudaGetSymbolAddress((void**)&pWKVt, g_WKVt);
    cudaGetSymbolAddress((void**)&pS,    g_scores);

    cudaFuncSetAttribute(gemm_h<false, false, true>,
                         cudaFuncAttributeMaxDynamicSharedMemorySize, SMEM_TOTAL);
    cudaFuncSetAttribute(gemm_h<true, false, true>,
                         cudaFuncAttributeMaxDynamicSharedMemorySize, SMEM_TOTAL);
    cudaFuncSetAttribute(gemm_h<false, true, false>,
                         cudaFuncAttributeMaxDynamicSharedMemorySize, SMEM_TOTAL);

    // 0) Prepass: q -> half; Wq, Wv transposed into concatenated [2048,1024] fp16
    f32_to_h<<<(B_ * S_ * D_ / 4 + 255) / 256, 256>>>(
        (const float4*)q, (uint2*)pq, B_ * S_ * D_ / 4);
    {
        const dim3 tgrid(D_ / 32, D_ / 32, 1);
        const dim3 tblk(32, 8);
        transpose_f2h<<<tgrid, tblk>>>(Wq, pWT, D_, D_);
        transpose_f2h<<<tgrid, tblk>>>(Wv, pWT + D_ * D_, D_, D_);
    }

    // 1) Fused projections: QKV[8192,2048] = q @ [Wq | Wv]  (B = [2048,1024])
    {
        const dim3 grid(2 * D_ / BN, (B_ * S_) / BM, 1);
        gemm_h<false, false, true><<<grid, 128, SMEM_TOTAL>>>(
            pq, pWT, pQKV, D_, D_, D_, 2 * D_, 1.0f, 0, 0, 0);
    }

    // 1b) Transpose WKV (= QKV cols 1024..2047) per batch: [S,D] -> [D,S]
    {
        const dim3 tgrid(D_ / 32, S_ / 32, B_);
        const dim3 tblk(32, 8);
        transpose_h2h<<<tgrid, tblk>>>(pQKV + D_, pWKVt, S_, D_, 2 * D_, S_,
                                       (size_t)S_ * 2 * D_, (size_t)D_ * S_);
    }

    // 2) Scores = WQ @ WKV^T / 32, causal tiles only (fp16 out)
    {
        const dim3 grid(S_ / BN, S_ / BM, B_);
        gemm_h<true, false, true><<<grid, 128, SMEM_TOTAL>>>(
            pQKV, pQKV + D_, pS, D_, 2 * D_, 2 * D_, S_, 1.0f / 32.0f,
            (size_t)S_ * 2 * D_, (size_t)S_ * 2 * D_, (size_t)S_ * S_);
    }

    // 3) Causal softmax in place (fp16)
    {
        const dim3 grid(S_, B_);
        softmax_h<<<grid, 256>>>(pS);
    }

    // 4) out = attn @ WKV (B = WKV^T as [N=D, K=S]); K truncated causally; fp32 out
    {
        const dim3 grid(D_ / BN, S_ / BM, B_);
        gemm_h<false, true, false><<<grid, 128, SMEM_TOTAL>>>(
            pS, pWKVt, out, S_, S_, S_, D_, 1.0f,
            (size_t)S_ * S_, (size_t)S_ * D_, (size_t)S_ * D_);
    }
}

// round 7
// speedup vs baseline: 4.1448x; 1.0318x over previous
#include <cuda_runtime.h>
#include <cuda_fp16.h>
#include <cstdint>

// Problem constants
#define B_ 4
#define S_ 2048
#define D_ 1024

// Scratch (device globals: allocation-free per harness rules)
__device__ __half g_qh [B_ * S_ * D_];            // 16 MB  q in fp16
__device__ __half g_WT [2 * D_ * D_];             // 4 MB   [WqT ; WvT] as [2048,1024]
__device__ __half g_QKV[(size_t)B_ * S_ * 2 * D_];// 32 MB  [8192, 2048]: WQ | WKV
__device__ __half g_WKVt[B_ * S_ * D_];           // 16 MB  WKV^T per batch [D, S]
__device__ __half g_scores[(size_t)B_ * S_ * S_]; // 32 MB  scores -> attn in place

// ---------------------------------------------------------------------------
// Helpers
// ---------------------------------------------------------------------------
__device__ __forceinline__ uint32_t smem_u32(const void* p) {
    uint32_t a;
    asm("{ .reg .u64 t; cvta.to.shared.u64 t, %1; cvt.u32.u64 %0, t; }" : "=r"(a) : "l"(p));
    return a;
}

__device__ __forceinline__ void mma_f16(float* c, const uint32_t* a, const uint32_t* b) {
    asm volatile(
        "mma.sync.aligned.m16n8k16.row.col.f32.f16.f16.f32 "
        "{%0,%1,%2,%3}, {%4,%5,%6,%7}, {%8,%9}, {%0,%1,%2,%3};"
        : "+f"(c[0]), "+f"(c[1]), "+f"(c[2]), "+f"(c[3])
        : "r"(a[0]), "r"(a[1]), "r"(a[2]), "r"(a[3]),
          "r"(b[0]), "r"(b[1]));
}

#define LDMX4(r0, r1, r2, r3, addr) \
    asm volatile("ldmatrix.sync.aligned.m8n8.x4.shared.b16 {%0,%1,%2,%3}, [%4];" \
        : "=r"(r0), "=r"(r1), "=r"(r2), "=r"(r3) : "r"(addr))

#define CP_ASYNC16(dst_u32, src_ptr) \
    asm volatile("cp.async.cg.shared.global [%0], [%1], 16;" \
        :: "r"(dst_u32), "l"(src_ptr) : "memory")
#define CP_COMMIT() asm volatile("cp.async.commit_group;" ::: "memory")
#define CP_WAIT1()  asm volatile("cp.async.wait_group 1;"  ::: "memory")

// ---------------------------------------------------------------------------
// FP16 pipelined GEMM: C = scale * A[M,K] @ B^T, B given as [N,K] (k-contig),
// fp32 accumulate. CTA tile 128x128, 4 warps (64x64 warp tile), KC=64,
// 3-stage cp.async ring, register double-buffered fragments, and fragment
// prefetch ACROSS chunk boundaries (boundary wait/sync hidden under ks3 MMAs).
// 2 CTAs/SM. Smem rows 128B, XOR-16B-chunk swizzle.
// CAUSAL: skip tiles with bn > bm. LIMITK: K truncated at (bm+1)*128.
// OUT_HALF: write __half (intermediates) else float (final output).
// ---------------------------------------------------------------------------
#define BM 128
#define BN 128
#define KC 64
#define A_STAGE (BM * 128)            // 16 KB
#define B_STAGE (BN * 128)            // 16 KB
#define B_OFF   (3 * A_STAGE)         // 49152
#define SMEM_TOTAL (3 * (A_STAGE + B_STAGE))  // 98304

template <bool CAUSAL, bool LIMITK, bool OUT_HALF>
__global__ void __launch_bounds__(128, 2)
gemm_h(const __half* __restrict__ A, const __half* __restrict__ Bn,
       void* __restrict__ Cv,
       int K, int lda, int ldb, int ldc, float scale,
       size_t aBatch, size_t bBatch, size_t cBatch)
{
    const int bm = blockIdx.y;
    const int bn = blockIdx.x;
    if (CAUSAL && bn > bm) return;   // whole CTA exits, no barriers yet

    extern __shared__ __align__(128) char smem[];
    const uint32_t sbase = smem_u32(smem);

    const int tid  = threadIdx.x;
    const int warp = tid >> 5;
    const int lane = tid & 31;
    const int wm = (warp >> 1) * 64;   // 2 warp-rows of 64
    const int wn = (warp & 1) * 64;    // 2 warp-cols of 64
    const int g  = lane >> 2;
    const int tq = lane & 3;

    const __half* Ab = A + aBatch * blockIdx.z + (size_t)(bm * BM) * lda;
    const __half* Bb = Bn + bBatch * blockIdx.z + (size_t)(bn * BN) * ldb;

    const int kEnd = LIMITK ? min(K, (bm + 1) * BM) : K;
    const int nc = kEnd / KC;

    float acc[4][8][4] = {};

    // ---- stage loader: 16B granules, swizzled dst (8 A + 8 B per thread) ----
    auto issue_stage = [&](int c) {
        if (c < nc) {
            const int s = c % 3;
            const int k0 = c * KC;
            const uint32_t da = sbase + s * A_STAGE;
            const uint32_t db = sbase + B_OFF + s * B_STAGE;
            #pragma unroll
            for (int i = 0; i < 8; i++) {           // A: 1024 granules
                const int gid = tid + i * 128;
                const int row = gid >> 3, ch = gid & 7;
                CP_ASYNC16(da + row * 128 + ((ch ^ (row & 7)) << 4),
                           Ab + (size_t)row * lda + k0 + ch * 8);
            }
            #pragma unroll
            for (int i = 0; i < 8; i++) {           // B: 1024 granules
                const int gid = tid + i * 128;
                const int row = gid >> 3, ch = gid & 7;
                CP_ASYNC16(db + row * 128 + ((ch ^ (row & 7)) << 4),
                           Bb + (size_t)row * ldb + k0 + ch * 8);
            }
        }
        CP_COMMIT();
    };

    // per-lane ldmatrix address invariants (patterns proven in rounds 4-6)
    const int l15  = lane & 15;
    const int lhi  = lane >> 4;          // A: k half select
    const int sx   = lane & 7;           // swizzle xor
    const int bkb  = (lane >> 3) & 1;    // B: k half select
    const int bRowOfs = ((lane >> 4) << 3) + (lane & 7);  // B: row within x4 group

    uint32_t af[2][4][4];
    uint32_t bf[2][8][2];

    // fragment loader: stage row bases passed explicitly (cross-chunk capable)
    auto load_frags = [&](uint32_t aRow, uint32_t bRow, int ks, int bu) {
        #pragma unroll
        for (int mi = 0; mi < 4; mi++) {
            const uint32_t addr = aRow + mi * (16 * 128) + (((2 * ks + lhi) ^ sx) << 4);
            LDMX4(af[bu][mi][0], af[bu][mi][1], af[bu][mi][2], af[bu][mi][3], addr);
        }
        #pragma unroll
        for (int nq = 0; nq < 4; nq++) {
            const uint32_t addr = bRow + nq * (16 * 128) + (((2 * ks + bkb) ^ sx) << 4);
            LDMX4(bf[bu][2 * nq][0], bf[bu][2 * nq][1],
                  bf[bu][2 * nq + 1][0], bf[bu][2 * nq + 1][1], addr);
        }
    };

    // ---- preamble: stages 0,1 in flight; frags(chunk0, ks0) resident ----
    issue_stage(0);
    issue_stage(1);
    CP_WAIT1();            // stage 0 arrived (own groups), then publish:
    __syncthreads();

    uint32_t aRowCur = sbase + (wm + l15) * 128;                  // stage 0
    uint32_t bRowCur = sbase + B_OFF + (wn + bRowOfs) * 128;
    load_frags(aRowCur, bRowCur, 0, 0);

    for (int c = 0; c < nc; c++) {
        #pragma unroll
        for (int ks = 0; ks < 4; ks++) {
            const int bu = ks & 1;
            if (ks < 3) {
                load_frags(aRowCur, bRowCur, ks + 1, bu ^ 1);
            } else if (c + 1 < nc) {
                // boundary: refill ring, sync, prefetch next chunk's ks0 frags.
                // slot (c+2)%3 was last read before chunk c's entry (lag <= 1 sync).
                issue_stage(c + 2);
                CP_WAIT1();        // stage c+1 complete (c+2 is the 1 in flight)
                __syncthreads();   // publish all threads' stage c+1 data
                const int sn = (c + 1) % 3;
                aRowCur = sbase + sn * A_STAGE + (wm + l15) * 128;
                bRowCur = sbase + B_OFF + sn * B_STAGE + (wn + bRowOfs) * 128;
                load_frags(aRowCur, bRowCur, 0, bu ^ 1);
            }
            #pragma unroll
            for (int mi = 0; mi < 4; mi++)
                #pragma unroll
                for (int ni = 0; ni < 8; ni++)
                    mma_f16(acc[mi][ni], af[bu][mi], bf[bu][ni]);
        }
    }

    // ---- epilogue ----
    #pragma unroll
    for (int mi = 0; mi < 4; mi++) {
        #pragma unroll
        for (int ni = 0; ni < 8; ni++) {
            const int row0 = bm * BM + wm + mi * 16 + g;
            const int col  = bn * BN + wn + ni * 8 + tq * 2;
            const float v0 = acc[mi][ni][0] * scale, v1 = acc[mi][ni][1] * scale;
            const float v2 = acc[mi][ni][2] * scale, v3 = acc[mi][ni][3] * scale;
            if (OUT_HALF) {
                __half* Cb = (__half*)Cv + cBatch * blockIdx.z;
                *reinterpret_cast<__half2*>(&Cb[(size_t)row0 * ldc + col]) =
                    __floats2half2_rn(v0, v1);
                *reinterpret_cast<__half2*>(&Cb[(size_t)(row0 + 8) * ldc + col]) =
                    __floats2half2_rn(v2, v3);
            } else {
                float* Cb = (float*)Cv + cBatch * blockIdx.z;
                *reinterpret_cast<float2*>(&Cb[(size_t)row0 * ldc + col]) = make_float2(v0, v1);
                *reinterpret_cast<float2*>(&Cb[(size_t)(row0 + 8) * ldc + col]) = make_float2(v2, v3);
            }
        }
    }
}

// ---------------------------------------------------------------------------
// Prepass: fp32 -> fp16 copy, vectorized
// ---------------------------------------------------------------------------
__global__ void __launch_bounds__(256) f32_to_h(const float4* __restrict__ src,
                                                uint2* __restrict__ dst, int n4)
{
    const int i = blockIdx.x * 256 + threadIdx.x;
    if (i < n4) {
        const float4 v = src[i];
        const __half2 h0 = __floats2half2_rn(v.x, v.y);
        const __half2 h1 = __floats2half2_rn(v.z, v.w);
        uint2 u;
        u.x = *reinterpret_cast<const uint32_t*>(&h0);
        u.y = *reinterpret_cast<const uint32_t*>(&h1);
        dst[i] = u;
    }
}

// ---------------------------------------------------------------------------
// Tiled transposes
// ---------------------------------------------------------------------------
__global__ void __launch_bounds__(256) transpose_f2h(const float* __restrict__ src,
                                                     __half* __restrict__ dst,
                                                     int R, int C)
{
    __shared__ float t[32][33];
    int x = blockIdx.x * 32 + threadIdx.x;
    int y = blockIdx.y * 32 + threadIdx.y;
    #pragma unroll
    for (int j = 0; j < 32; j += 8)
        t[threadIdx.y + j][threadIdx.x] = src[(size_t)(y + j) * C + x];
    __syncthreads();
    x = blockIdx.y * 32 + threadIdx.x;
    y = blockIdx.x * 32 + threadIdx.y;
    #pragma unroll
    for (int j = 0; j < 32; j += 8)
        dst[(size_t)(y + j) * R + x] = __float2half_rn(t[threadIdx.x][threadIdx.y + j]);
}

// src [R x C] with row stride srcLd -> dst [C x R] with row stride dstLd, batched
__global__ void __launch_bounds__(256) transpose_h2h(const __half* __restrict__ src,
                                                     __half* __restrict__ dst,
                                                     int R, int C, int srcLd, int dstLd,
                                                     size_t srcBatch, size_t dstBatch)
{
    __shared__ float t[32][33];
    src += srcBatch * blockIdx.z;
    dst += dstBatch * blockIdx.z;
    int x = blockIdx.x * 32 + threadIdx.x;
    int y = blockIdx.y * 32 + threadIdx.y;
    #pragma unroll
    for (int j = 0; j < 32; j += 8)
        t[threadIdx.y + j][threadIdx.x] = __half2float(src[(size_t)(y + j) * srcLd + x]);
    __syncthreads();
    x = blockIdx.y * 32 + threadIdx.x;
    y = blockIdx.x * 32 + threadIdx.y;
    #pragma unroll
    for (int j = 0; j < 32; j += 8)
        dst[(size_t)(y + j) * dstLd + x] = __float2half_rn(t[threadIdx.x][threadIdx.y + j]);
}

// ---------------------------------------------------------------------------
// Causal row softmax on fp16 scores (fp32 math). Zero-fills to 128-boundary
// so the out-GEMM's truncated K loop reads exact zeros.
// ---------------------------------------------------------------------------
__global__ void __launch_bounds__(256) softmax_h(__half* __restrict__ scores)
{
    __shared__ float red[8];
    __shared__ float bcast;

    const int q = blockIdx.x;
    __half* row = scores + ((size_t)blockIdx.y * S_ + q) * S_;
    const int len = q + 1;
    const int tid = threadIdx.x;

    float m = -3.4e38f;
    for (int i = tid; i < len; i += 256) m = fmaxf(m, __half2float(row[i]));
    #pragma unroll
    for (int o = 16; o; o >>= 1) m = fmaxf(m, __shfl_xor_sync(0xffffffffu, m, o));
    if ((tid & 31) == 0) red[tid >> 5] = m;
    __syncthreads();
    if (tid == 0) {
        float v = red[0];
        #pragma unroll
        for (int i = 1; i < 8; i++) v = fmaxf(v, red[i]);
        bcast = v;
    }
    __syncthreads();
    m = bcast;

    float sum = 0.f;
    for (int i = tid; i < len; i += 256) sum += __expf(__half2float(row[i]) - m);
    #pragma unroll
    for (int o = 16; o; o >>= 1) sum += __shfl_xor_sync(0xffffffffu, sum, o);
    __syncthreads();
    if ((tid & 31) == 0) red[tid >> 5] = sum;
    __syncthreads();
    if (tid == 0) {
        float v = 0.f;
        #pragma unroll
        for (int i = 0; i < 8; i++) v += red[i];
        bcast = 1.f / v;
    }
    __syncthreads();
    const float inv = bcast;

    const int tileEnd = ((q >> 7) + 1) << 7;   // end of the 128-row K-block
    for (int i = tid; i < tileEnd; i += 256)
        row[i] = (i < len) ? __float2half_rn(__expf(__half2float(row[i]) - m) * inv)
                           : __half(0.f);
}

// ---------------------------------------------------------------------------
// Launch
// ---------------------------------------------------------------------------
extern "C" void kernel_launch(void* const* d_in, const int* in_sizes, int n_in,
                              void* d_out, int out_size)
{
    (void)in_sizes; (void)n_in; (void)out_size;
    const float* q  = (const float*)d_in[0];
    const float* Wq = (const float*)d_in[1];
    // d_in[2] = Wk (unused by reference), d_in[4] = mask (causal, analytic)
    const float* Wv = (const float*)d_in[3];
    float* out = (float*)d_out;

    __half *pq, *pWT, *pQKV, *pWKVt, *pS;
    cudaGetSymbolAddress((void**)&pq,    g_qh);
    cudaGetSymbolAddress((void**)&pWT,   g_WT);
    cudaGetSymbolAddress((void**)&pQKV,  g_QKV);
    cudaGetSymbolAddress((void**)&pWKVt, g_WKVt);
    cudaGetSymbolAddress((void**)&pS,    g_scores);

    cudaFuncSetAttribute(gemm_h<false, false, true>,
                         cudaFuncAttributeMaxDynamicSharedMemorySize, SMEM_TOTAL);
    cudaFuncSetAttribute(gemm_h<true, false, true>,
                         cudaFuncAttributeMaxDynamicSharedMemorySize, SMEM_TOTAL);
    cudaFuncSetAttribute(gemm_h<false, true, false>,
                         cudaFuncAttributeMaxDynamicSharedMemorySize, SMEM_TOTAL);

    // 0) Prepass: q -> half; Wq, Wv transposed into concatenated [2048,1024] fp16
    f32_to_h<<<(B_ * S_ * D_ / 4 + 255) / 256, 256>>>(
        (const float4*)q, (uint2*)pq, B_ * S_ * D_ / 4);
    {
        const dim3 tgrid(D_ / 32, D_ / 32, 1);
        const dim3 tblk(32, 8);
        transpose_f2h<<<tgrid, tblk>>>(Wq, pWT, D_, D_);
        transpose_f2h<<<tgrid, tblk>>>(Wv, pWT + D_ * D_, D_, D_);
    }

    // 1) Fused projections: QKV[8192,2048] = q @ [Wq | Wv]  (B = [2048,1024])
    {
        const dim3 grid(2 * D_ / BN, (B_ * S_) / BM, 1);
        gemm_h<false, false, true><<<grid, 128, SMEM_TOTAL>>>(
            pq, pWT, pQKV, D_, D_, D_, 2 * D_, 1.0f, 0, 0, 0);
    }

    // 1b) Transpose WKV (= QKV cols 1024..2047) per batch: [S,D] -> [D,S]
    {
        const dim3 tgrid(D_ / 32, S_ / 32, B_);
        const dim3 tblk(32, 8);
        transpose_h2h<<<tgrid, tblk>>>(pQKV + D_, pWKVt, S_, D_, 2 * D_, S_,
                                       (size_t)S_ * 2 * D_, (size_t)D_ * S_);
    }

    // 2) Scores = WQ @ WKV^T / 32, causal tiles only (fp16 out)
    {
        const dim3 grid(S_ / BN, S_ / BM, B_);
        gemm_h<true, false, true><<<grid, 128, SMEM_TOTAL>>>(
            pQKV, pQKV + D_, pS, D_, 2 * D_, 2 * D_, S_, 1.0f / 32.0f,
            (size_t)S_ * 2 * D_, (size_t)S_ * 2 * D_, (size_t)S_ * S_);
    }

    // 3) Causal softmax in place (fp16)
    {
        const dim3 grid(S_, B_);
        softmax_h<<<grid, 256>>>(pS);
    }

    // 4) out = attn @ WKV (B = WKV^T as [N=D, K=S]); K truncated causally; fp32 out
    {
        const dim3 grid(D_ / BN, S_ / BM, B_);
        gemm_h<false, true, false><<<grid, 128, SMEM_TOTAL>>>(
            pS, pWKVt, out, S_, S_, S_, D_, 1.0f,
            (size_t)S_ * S_, (size_t)S_ * D_, (size_t)S_ * D_);
    }
}

// round 8
// speedup vs baseline: 4.5190x; 1.0903x over previous
#include <cuda_runtime.h>
#include <cuda_fp16.h>
#include <cstdint>

// Problem constants
#define B_ 4
#define S_ 2048
#define D_ 1024

// Scratch (device globals: allocation-free per harness rules)
__device__ __half g_qh [B_ * S_ * D_];            // 16 MB  q in fp16
__device__ __half g_WT [2 * D_ * D_];             // 4 MB   [WqT ; WvT] as [2048,1024]
__device__ __half g_QKV[(size_t)B_ * S_ * 2 * D_];// 32 MB  [8192, 2048]: WQ | WKV
__device__ __half g_scores[(size_t)B_ * S_ * S_]; // 32 MB  scores -> attn in place

// ---------------------------------------------------------------------------
// Helpers
// ---------------------------------------------------------------------------
__device__ __forceinline__ uint32_t smem_u32(const void* p) {
    uint32_t a;
    asm("{ .reg .u64 t; cvta.to.shared.u64 t, %1; cvt.u32.u64 %0, t; }" : "=r"(a) : "l"(p));
    return a;
}

__device__ __forceinline__ void mma_f16(float* c, const uint32_t* a, const uint32_t* b) {
    asm volatile(
        "mma.sync.aligned.m16n8k16.row.col.f32.f16.f16.f32 "
        "{%0,%1,%2,%3}, {%4,%5,%6,%7}, {%8,%9}, {%0,%1,%2,%3};"
        : "+f"(c[0]), "+f"(c[1]), "+f"(c[2]), "+f"(c[3])
        : "r"(a[0]), "r"(a[1]), "r"(a[2]), "r"(a[3]),
          "r"(b[0]), "r"(b[1]));
}

#define LDMX4(r0, r1, r2, r3, addr) \
    asm volatile("ldmatrix.sync.aligned.m8n8.x4.shared.b16 {%0,%1,%2,%3}, [%4];" \
        : "=r"(r0), "=r"(r1), "=r"(r2), "=r"(r3) : "r"(addr))

#define LDMX4T(r0, r1, r2, r3, addr) \
    asm volatile("ldmatrix.sync.aligned.m8n8.x4.trans.shared.b16 {%0,%1,%2,%3}, [%4];" \
        : "=r"(r0), "=r"(r1), "=r"(r2), "=r"(r3) : "r"(addr))

#define CP_ASYNC16(dst_u32, src_ptr) \
    asm volatile("cp.async.cg.shared.global [%0], [%1], 16;" \
        :: "r"(dst_u32), "l"(src_ptr) : "memory")
#define CP_COMMIT() asm volatile("cp.async.commit_group;" ::: "memory")
#define CP_WAIT1()  asm volatile("cp.async.wait_group 1;"  ::: "memory")

// ---------------------------------------------------------------------------
// FP16 pipelined GEMM: C = scale * A[M,K] @ B', fp32 accumulate.
//   TRANSB_LDM = false: B given as [N,K] (k-contiguous rows), ldmatrix normal.
//   TRANSB_LDM = true : B given as [K,N] (n-contiguous rows), ldmatrix.trans,
//                       256B smem rows with XOR-16B swizzle.
// CTA tile 128x128, 4 warps (64x64 warp tile), KC=64, 3-stage cp.async ring,
// register double-buffered fragments + cross-chunk fragment prefetch, 2 CTAs/SM.
// CAUSAL: skip tiles with bn > bm. LIMITK: K truncated at (bm+1)*128.
// OUT_HALF: write __half (intermediates) else float (final output).
// ---------------------------------------------------------------------------
#define BM 128
#define BN 128
#define KC 64
#define A_STAGE (BM * 128)            // 16 KB
#define B_STAGE (BN * 128)            // 16 KB (both layouts: 16 KB per stage)
#define B_OFF   (3 * A_STAGE)         // 49152
#define SMEM_TOTAL (3 * (A_STAGE + B_STAGE))  // 98304

template <bool CAUSAL, bool LIMITK, bool OUT_HALF, bool TRANSB_LDM>
__global__ void __launch_bounds__(128, 2)
gemm_h(const __half* __restrict__ A, const __half* __restrict__ Bn,
       void* __restrict__ Cv,
       int K, int lda, int ldb, int ldc, float scale,
       size_t aBatch, size_t bBatch, size_t cBatch)
{
    const int bm = blockIdx.y;
    const int bn = blockIdx.x;
    if (CAUSAL && bn > bm) return;   // whole CTA exits, no barriers yet

    extern __shared__ __align__(128) char smem[];
    const uint32_t sbase = smem_u32(smem);

    const int tid  = threadIdx.x;
    const int warp = tid >> 5;
    const int lane = tid & 31;
    const int wm = (warp >> 1) * 64;   // 2 warp-rows of 64
    const int wn = (warp & 1) * 64;    // 2 warp-cols of 64
    const int g  = lane >> 2;
    const int tq = lane & 3;

    const __half* Ab = A + aBatch * blockIdx.z + (size_t)(bm * BM) * lda;
    // non-trans: B row base = tile n row; trans: B col base = tile n col
    const __half* Bb = Bn + bBatch * blockIdx.z +
                       (TRANSB_LDM ? (size_t)(bn * BN) : (size_t)(bn * BN) * ldb);

    const int kEnd = LIMITK ? min(K, (bm + 1) * BM) : K;
    const int nc = kEnd / KC;

    float acc[4][8][4] = {};

    // ---- stage loader: 16B granules, swizzled dst ----
    auto issue_stage = [&](int c) {
        if (c < nc) {
            const int s = c % 3;
            const int k0 = c * KC;
            const uint32_t da = sbase + s * A_STAGE;
            const uint32_t db = sbase + B_OFF + s * B_STAGE;
            #pragma unroll
            for (int i = 0; i < 8; i++) {           // A: 1024 granules, 128B rows
                const int gid = tid + i * 128;
                const int row = gid >> 3, ch = gid & 7;
                CP_ASYNC16(da + row * 128 + ((ch ^ (row & 7)) << 4),
                           Ab + (size_t)row * lda + k0 + ch * 8);
            }
            if (TRANSB_LDM) {
                // B tile: KC=64 k-rows x 128 n-cols, 256B rows, 16 chunks/row
                #pragma unroll
                for (int i = 0; i < 8; i++) {
                    const int gid = tid + i * 128;
                    const int row = gid >> 4, ch = gid & 15;
                    const uint32_t dst = db + row * 256 + ((ch & 8) << 4) +
                                         (((ch & 7) ^ (row & 7)) << 4);
                    CP_ASYNC16(dst, Bb + (size_t)(k0 + row) * ldb + ch * 8);
                }
            } else {
                // B tile: 128 n-rows x KC k, 128B rows
                #pragma unroll
                for (int i = 0; i < 8; i++) {
                    const int gid = tid + i * 128;
                    const int row = gid >> 3, ch = gid & 7;
                    CP_ASYNC16(db + row * 128 + ((ch ^ (row & 7)) << 4),
                               Bb + (size_t)row * ldb + k0 + ch * 8);
                }
            }
        }
        CP_COMMIT();
    };

    // per-lane ldmatrix address invariants
    const int l15  = lane & 15;
    const int lhi  = lane >> 4;          // A: k half select
    const int sx   = lane & 7;           // swizzle xor (128B rows)
    const int bkb  = (lane >> 3) & 1;    // B non-trans: k half select
    const int bRowOfs = ((lane >> 4) << 3) + (lane & 7);  // B non-trans row
    // B trans: lane -> (k row within 16, n-chunk add)
    const int tRow = lane & 15;          // k row 0..15
    const int tCh  = lane >> 4;          // +0/+1 16B chunk (n 8..15)

    uint32_t af[2][4][4];
    uint32_t bf[2][8][2];

    // fragment loader for one k16 step of the stage starting at aSB/bSB
    auto load_frags = [&](uint32_t aSB, uint32_t bSB, int ks, int bu) {
        const uint32_t aRow = aSB + (wm + l15) * 128;
        #pragma unroll
        for (int mi = 0; mi < 4; mi++) {
            const uint32_t addr = aRow + mi * (16 * 128) + (((2 * ks + lhi) ^ sx) << 4);
            LDMX4(af[bu][mi][0], af[bu][mi][1], af[bu][mi][2], af[bu][mi][3], addr);
        }
        if (TRANSB_LDM) {
            const int krow = 16 * ks + tRow;
            const uint32_t rBase = bSB + krow * 256;
            #pragma unroll
            for (int q = 0; q < 4; q++) {
                const int ch = (wn >> 3) + 2 * q + tCh;   // 16B chunk (n index /8)
                const uint32_t addr = rBase + ((ch & 8) << 4) +
                                      (((ch & 7) ^ (tRow & 7)) << 4);
                LDMX4T(bf[bu][2 * q][0], bf[bu][2 * q][1],
                       bf[bu][2 * q + 1][0], bf[bu][2 * q + 1][1], addr);
            }
        } else {
            const uint32_t bRow = bSB + (wn + bRowOfs) * 128;
            #pragma unroll
            for (int nq = 0; nq < 4; nq++) {
                const uint32_t addr = bRow + nq * (16 * 128) + (((2 * ks + bkb) ^ sx) << 4);
                LDMX4(bf[bu][2 * nq][0], bf[bu][2 * nq][1],
                      bf[bu][2 * nq + 1][0], bf[bu][2 * nq + 1][1], addr);
            }
        }
    };

    // ---- preamble ----
    issue_stage(0);
    issue_stage(1);
    CP_WAIT1();
    __syncthreads();

    uint32_t aSB = sbase, bSB = sbase + B_OFF;
    load_frags(aSB, bSB, 0, 0);

    for (int c = 0; c < nc; c++) {
        #pragma unroll
        for (int ks = 0; ks < 4; ks++) {
            const int bu = ks & 1;
            if (ks < 3) {
                load_frags(aSB, bSB, ks + 1, bu ^ 1);
            } else if (c + 1 < nc) {
                issue_stage(c + 2);
                CP_WAIT1();
                __syncthreads();
                const int sn = (c + 1) % 3;
                aSB = sbase + sn * A_STAGE;
                bSB = sbase + B_OFF + sn * B_STAGE;
                load_frags(aSB, bSB, 0, bu ^ 1);
            }
            #pragma unroll
            for (int mi = 0; mi < 4; mi++)
                #pragma unroll
                for (int ni = 0; ni < 8; ni++)
                    mma_f16(acc[mi][ni], af[bu][mi], bf[bu][ni]);
        }
    }

    // ---- epilogue ----
    #pragma unroll
    for (int mi = 0; mi < 4; mi++) {
        #pragma unroll
        for (int ni = 0; ni < 8; ni++) {
            const int row0 = bm * BM + wm + mi * 16 + g;
            const int col  = bn * BN + wn + ni * 8 + tq * 2;
            const float v0 = acc[mi][ni][0] * scale, v1 = acc[mi][ni][1] * scale;
            const float v2 = acc[mi][ni][2] * scale, v3 = acc[mi][ni][3] * scale;
            if (OUT_HALF) {
                __half* Cb = (__half*)Cv + cBatch * blockIdx.z;
                *reinterpret_cast<__half2*>(&Cb[(size_t)row0 * ldc + col]) =
                    __floats2half2_rn(v0, v1);
                *reinterpret_cast<__half2*>(&Cb[(size_t)(row0 + 8) * ldc + col]) =
                    __floats2half2_rn(v2, v3);
            } else {
                float* Cb = (float*)Cv + cBatch * blockIdx.z;
                *reinterpret_cast<float2*>(&Cb[(size_t)row0 * ldc + col]) = make_float2(v0, v1);
                *reinterpret_cast<float2*>(&Cb[(size_t)(row0 + 8) * ldc + col]) = make_float2(v2, v3);
            }
        }
    }
}

// ---------------------------------------------------------------------------
// Prepass: fp32 -> fp16 copy, vectorized
// ---------------------------------------------------------------------------
__global__ void __launch_bounds__(256) f32_to_h(const float4* __restrict__ src,
                                                uint2* __restrict__ dst, int n4)
{
    const int i = blockIdx.x * 256 + threadIdx.x;
    if (i < n4) {
        const float4 v = src[i];
        const __half2 h0 = __floats2half2_rn(v.x, v.y);
        const __half2 h1 = __floats2half2_rn(v.z, v.w);
        uint2 u;
        u.x = *reinterpret_cast<const uint32_t*>(&h0);
        u.y = *reinterpret_cast<const uint32_t*>(&h1);
        dst[i] = u;
    }
}

// ---------------------------------------------------------------------------
// Tiled transpose: fp32 src -> fp16 dst (weights only)
// ---------------------------------------------------------------------------
__global__ void __launch_bounds__(256) transpose_f2h(const float* __restrict__ src,
                                                     __half* __restrict__ dst,
                                                     int R, int C)
{
    __shared__ float t[32][33];
    int x = blockIdx.x * 32 + threadIdx.x;
    int y = blockIdx.y * 32 + threadIdx.y;
    #pragma unroll
    for (int j = 0; j < 32; j += 8)
        t[threadIdx.y + j][threadIdx.x] = src[(size_t)(y + j) * C + x];
    __syncthreads();
    x = blockIdx.y * 32 + threadIdx.x;
    y = blockIdx.x * 32 + threadIdx.y;
    #pragma unroll
    for (int j = 0; j < 32; j += 8)
        dst[(size_t)(y + j) * R + x] = __float2half_rn(t[threadIdx.x][threadIdx.y + j]);
}

// ---------------------------------------------------------------------------
// Causal row softmax (fp16 in/out, fp32 math), register-cached single pass:
// one gmem read + one gmem write. Zero-fills to 128-boundary.
// ---------------------------------------------------------------------------
__global__ void __launch_bounds__(128) softmax_h(__half* __restrict__ scores)
{
    __shared__ float red[4];
    __shared__ float bcast;

    const int q = blockIdx.x;
    __half2* row = reinterpret_cast<__half2*>(
        scores + ((size_t)blockIdx.y * S_ + q) * S_);
    const int len = q + 1;
    const int np  = (len + 1) >> 1;     // half2 pairs containing valid data
    const int tid = threadIdx.x;

    float vx[8], vy[8];

    // read + max
    float m = -3.4e38f;
    #pragma unroll
    for (int i = 0; i < 8; i++) {
        const int p = tid + (i << 7);
        if (p < np) {
            const float2 f = __half22float2(row[p]);
            vx[i] = f.x;
            vy[i] = (2 * p + 1 < len) ? f.y : -3.4e38f;
            m = fmaxf(m, fmaxf(vx[i], vy[i]));
        } else {
            vx[i] = -3.4e38f; vy[i] = -3.4e38f;
        }
    }
    #pragma unroll
    for (int o = 16; o; o >>= 1) m = fmaxf(m, __shfl_xor_sync(0xffffffffu, m, o));
    if ((tid & 31) == 0) red[tid >> 5] = m;
    __syncthreads();
    m = fmaxf(fmaxf(red[0], red[1]), fmaxf(red[2], red[3]));

    // exp + sum (masked lanes: exp(-huge - m) underflows to exactly 0)
    float s = 0.f;
    #pragma unroll
    for (int i = 0; i < 8; i++) {
        vx[i] = __expf(vx[i] - m);
        vy[i] = __expf(vy[i] - m);
        s += vx[i] + vy[i];
    }
    #pragma unroll
    for (int o = 16; o; o >>= 1) s += __shfl_xor_sync(0xffffffffu, s, o);
    __syncthreads();
    if ((tid & 31) == 0) red[tid >> 5] = s;
    __syncthreads();
    if (tid == 0) bcast = 1.f / (red[0] + red[1] + red[2] + red[3]);
    __syncthreads();
    const float inv = bcast;

    // write (normalized attn; zeros through end of diagonal 128-tile)
    const int tEnd2 = (((q >> 7) + 1) << 7) >> 1;  // pairs to write
    #pragma unroll
    for (int i = 0; i < 8; i++) {
        const int p = tid + (i << 7);
        if (p < tEnd2)
            row[p] = __floats2half2_rn(vx[i] * inv, vy[i] * inv);
    }
}

// ---------------------------------------------------------------------------
// Launch
// ---------------------------------------------------------------------------
extern "C" void kernel_launch(void* const* d_in, const int* in_sizes, int n_in,
                              void* d_out, int out_size)
{
    (void)in_sizes; (void)n_in; (void)out_size;
    const float* q  = (const float*)d_in[0];
    const float* Wq = (const float*)d_in[1];
    // d_in[2] = Wk (unused by reference), d_in[4] = mask (causal, analytic)
    const float* Wv = (const float*)d_in[3];
    float* out = (float*)d_out;

    __half *pq, *pWT, *pQKV, *pS;
    cudaGetSymbolAddress((void**)&pq,   g_qh);
    cudaGetSymbolAddress((void**)&pWT,  g_WT);
    cudaGetSymbolAddress((void**)&pQKV, g_QKV);
    cudaGetSymbolAddress((void**)&pS,   g_scores);

    cudaFuncSetAttribute(gemm_h<false, false, true, false>,
                         cudaFuncAttributeMaxDynamicSharedMemorySize, SMEM_TOTAL);
    cudaFuncSetAttribute(gemm_h<true, false, true, false>,
                         cudaFuncAttributeMaxDynamicSharedMemorySize, SMEM_TOTAL);
    cudaFuncSetAttribute(gemm_h<false, true, false, true>,
                         cudaFuncAttributeMaxDynamicSharedMemorySize, SMEM_TOTAL);

    // 0) Prepass: q -> half; Wq, Wv transposed into concatenated [2048,1024] fp16
    f32_to_h<<<(B_ * S_ * D_ / 4 + 255) / 256, 256>>>(
        (const float4*)q, (uint2*)pq, B_ * S_ * D_ / 4);
    {
        const dim3 tgrid(D_ / 32, D_ / 32, 1);
        const dim3 tblk(32, 8);
        transpose_f2h<<<tgrid, tblk>>>(Wq, pWT, D_, D_);
        transpose_f2h<<<tgrid, tblk>>>(Wv, pWT + D_ * D_, D_, D_);
    }

    // 1) Fused projections: QKV[8192,2048] = q @ [Wq | Wv]  (B = [2048,1024])
    {
        const dim3 grid(2 * D_ / BN, (B_ * S_) / BM, 1);
        gemm_h<false, false, true, false><<<grid, 128, SMEM_TOTAL>>>(
            pq, pWT, pQKV, D_, D_, D_, 2 * D_, 1.0f, 0, 0, 0);
    }

    // 2) Scores = WQ @ WKV^T / 32, causal tiles only (fp16 out)
    {
        const dim3 grid(S_ / BN, S_ / BM, B_);
        gemm_h<true, false, true, false><<<grid, 128, SMEM_TOTAL>>>(
            pQKV, pQKV + D_, pS, D_, 2 * D_, 2 * D_, S_, 1.0f / 32.0f,
            (size_t)S_ * 2 * D_, (size_t)S_ * 2 * D_, (size_t)S_ * S_);
    }

    // 3) Causal softmax in place (fp16, register-cached)
    {
        const dim3 grid(S_, B_);
        softmax_h<<<grid, 128>>>(pS);
    }

    // 4) out = attn @ WKV: B consumed directly as [K=S, N=D] (n-contig) via
    //    ldmatrix.trans — no transpose pass. K truncated causally; fp32 out.
    {
        const dim3 grid(D_ / BN, S_ / BM, B_);
        gemm_h<false, true, false, true><<<grid, 128, SMEM_TOTAL>>>(
            pS, pQKV + D_, out, S_, S_, 2 * D_, D_, 1.0f,
            (size_t)S_ * S_, (size_t)S_ * 2 * D_, (size_t)S_ * D_);
    }
}